// round 11
// baseline (speedup 1.0000x reference)
#include <cuda_runtime.h>
#include <cuda_bf16.h>
#include <cstdint>

// ---------------------------------------------------------------------------
// Problem dimensions (fixed by the reference)
// ---------------------------------------------------------------------------
#define BATCH     32
#define HEADS     12
#define SEQ       576
#define HD        64
#define CDIM      768
#define MROWS     (BATCH * SEQ)      // 18432
#define QKV_COLS  (3 * CDIM)         // 2304
#define GRID_SZ   24
#define MSIZE     47
#define MASK_D    12
#define SOFT_SCALE 0.125f

// ---------------------------------------------------------------------------
// Scratch (device globals)
// ---------------------------------------------------------------------------
__device__ float g_bm[(size_t)HEADS * SEQ * SEQ];                 // 16 MB
__device__ __nv_bfloat16 g_qkvh[(size_t)MROWS * QKV_COLS];
__device__ __nv_bfloat16 g_qkvl[(size_t)MROWS * QKV_COLS];
__device__ __nv_bfloat16 g_xh[(size_t)MROWS * CDIM];
__device__ __nv_bfloat16 g_xl[(size_t)MROWS * CDIM];
__device__ __nv_bfloat16 g_x2h[(size_t)MROWS * CDIM];
__device__ __nv_bfloat16 g_x2l[(size_t)MROWS * CDIM];
__device__ __nv_bfloat16 g_wqkvTh[(size_t)QKV_COLS * CDIM];
__device__ __nv_bfloat16 g_wqkvTl[(size_t)QKV_COLS * CDIM];
__device__ __nv_bfloat16 g_wprojTh[(size_t)CDIM * CDIM];
__device__ __nv_bfloat16 g_wprojTl[(size_t)CDIM * CDIM];

// ---------------------------------------------------------------------------
// Helpers
// ---------------------------------------------------------------------------
__device__ __forceinline__ void cp_async16(uint32_t smem_dst, const void* gptr) {
    asm volatile("cp.async.cg.shared.global [%0], [%1], 16;"
                 :: "r"(smem_dst), "l"(gptr));
}
__device__ __forceinline__ void cp_commit() { asm volatile("cp.async.commit_group;"); }
__device__ __forceinline__ void cp_wait0()  { asm volatile("cp.async.wait_group 0;"); }
__device__ __forceinline__ void cp_wait1()  { asm volatile("cp.async.wait_group 1;"); }

__device__ __forceinline__ void mma_bf16(
    float* c, uint32_t a0, uint32_t a1, uint32_t a2, uint32_t a3,
    uint32_t b0, uint32_t b1)
{
    asm volatile(
        "mma.sync.aligned.m16n8k16.row.col.f32.bf16.bf16.f32 "
        "{%0,%1,%2,%3}, {%4,%5,%6,%7}, {%8,%9}, {%0,%1,%2,%3};"
        : "+f"(c[0]), "+f"(c[1]), "+f"(c[2]), "+f"(c[3])
        : "r"(a0), "r"(a1), "r"(a2), "r"(a3), "r"(b0), "r"(b1));
}

__device__ __forceinline__ void ldsm_x4(uint32_t& r0, uint32_t& r1,
                                        uint32_t& r2, uint32_t& r3,
                                        uint32_t addr) {
    asm volatile("ldmatrix.sync.aligned.m8n8.x4.shared.b16 {%0,%1,%2,%3}, [%4];"
                 : "=r"(r0), "=r"(r1), "=r"(r2), "=r"(r3) : "r"(addr));
}
__device__ __forceinline__ void ldsm_x4_t(uint32_t& r0, uint32_t& r1,
                                          uint32_t& r2, uint32_t& r3,
                                          uint32_t addr) {
    asm volatile("ldmatrix.sync.aligned.m8n8.x4.trans.shared.b16 {%0,%1,%2,%3}, [%4];"
                 : "=r"(r0), "=r"(r1), "=r"(r2), "=r"(r3) : "r"(addr));
}

__device__ __forceinline__ void split_bf16(float v, __nv_bfloat16& h, __nv_bfloat16& l) {
    h = __float2bfloat16(v);
    l = __float2bfloat16(v - __bfloat162float(h));
}
__device__ __forceinline__ uint32_t pack2(float a, float b) {
    __nv_bfloat162 t = __floats2bfloat162_rn(a, b);
    return *(uint32_t*)&t;
}

// ---------------------------------------------------------------------------
// Prepass kernels
// ---------------------------------------------------------------------------
__global__ void split_kernel(const float* __restrict__ in,
                             __nv_bfloat16* __restrict__ hi,
                             __nv_bfloat16* __restrict__ lo, int n4) {
    int t = blockIdx.x * 256 + threadIdx.x;
    if (t >= n4) return;
    float4 v = *(const float4*)(in + (size_t)t * 4);
    __nv_bfloat16 h[4], l[4];
    split_bf16(v.x, h[0], l[0]);
    split_bf16(v.y, h[1], l[1]);
    split_bf16(v.z, h[2], l[2]);
    split_bf16(v.w, h[3], l[3]);
    *(ushort4*)(hi + (size_t)t * 4) = *(ushort4*)h;
    *(ushort4*)(lo + (size_t)t * 4) = *(ushort4*)l;
}

__global__ void transpose_split_kernel(const float* __restrict__ src,
                                       __nv_bfloat16* __restrict__ dstH,
                                       __nv_bfloat16* __restrict__ dstL,
                                       int R, int C) {
    __shared__ float t[32][33];
    int bx = blockIdx.x * 32, by = blockIdx.y * 32;
#pragma unroll
    for (int i = 0; i < 32; i += 8)
        t[threadIdx.y + i][threadIdx.x] =
            src[(size_t)(by + threadIdx.y + i) * C + bx + threadIdx.x];
    __syncthreads();
#pragma unroll
    for (int i = 0; i < 32; i += 8) {
        float v = t[threadIdx.x][threadIdx.y + i];
        __nv_bfloat16 h, l;
        split_bf16(v, h, l);
        size_t o = (size_t)(bx + threadIdx.y + i) * R + by + threadIdx.x;
        dstH[o] = h;
        dstL[o] = l;
    }
}

__global__ void biasmask_kernel(const float* __restrict__ rel_table) {
    int t = blockIdx.x * 256 + threadIdx.x;
    if (t >= HEADS * SEQ * SEQ) return;
    int h = t / (SEQ * SEQ);
    int r = t - h * (SEQ * SEQ);
    int q = r / SEQ;
    int k = r - q * SEQ;
    int qr = q / GRID_SZ, qc = q - qr * GRID_SZ;
    int kr = k / GRID_SZ, kc = k - kr * GRID_SZ;
    int dr = kr - qr, dc = kc - qc;
    int idx = (dr + GRID_SZ - 1) * MSIZE + (dc + GRID_SZ - 1);
    float v = rel_table[idx * HEADS + h];
    int cheb = max(abs(dr), abs(dc));
    if (cheb > MASK_D) v += -100.0f;
    g_bm[t] = v;
}

// ---------------------------------------------------------------------------
// bf16x3 tensor-core GEMM — 128x256 CTA tile, 512 threads (16 warps 2m x 8n).
// Halves A-tile L2 re-reads vs the 128x128 version (the measured limiter).
// ---------------------------------------------------------------------------
#define KDIM 768
#define GBK  32
#define NST  (KDIM / GBK)
#define TROW 40
#define TILE_A_BYTES (128 * TROW * 2)   // 10240
#define TILE_B_BYTES (256 * TROW * 2)   // 20480
#define STAGE_BYTES (2 * TILE_A_BYTES + 2 * TILE_B_BYTES)   // 61440
#define G_SMEM_BYTES (2 * STAGE_BYTES)                      // 122880
#define OFF_GA_H 0
#define OFF_GA_L TILE_A_BYTES
#define OFF_GB_H (2 * TILE_A_BYTES)
#define OFF_GB_L (2 * TILE_A_BYTES + TILE_B_BYTES)

__global__ __launch_bounds__(512, 1)
void gemm_bf16x3(const __nv_bfloat16* __restrict__ Ah,
                 const __nv_bfloat16* __restrict__ Al,
                 const __nv_bfloat16* __restrict__ Bh,
                 const __nv_bfloat16* __restrict__ Bl,
                 const float* __restrict__ bias,
                 float* __restrict__ Cf,
                 __nv_bfloat16* __restrict__ Ch,
                 __nv_bfloat16* __restrict__ Cl, int Nt) {
    extern __shared__ __nv_bfloat16 smb[];
    const uint32_t smem0 = (uint32_t)__cvta_generic_to_shared(smb);

    const int tid = threadIdx.x;
    const int wid = tid >> 5;
    const int lane = tid & 31;
    const int g = lane >> 2;
    const int tig = lane & 3;
    const int l8 = lane & 7;
    const int sel = lane >> 3;
    const int wm = wid & 1;          // 2 m-slices of 64
    const int wn = wid >> 1;         // 8 n-slices of 32
    const int tileM = blockIdx.y, tileN = blockIdx.x;

    const __nv_bfloat16* Abh = Ah + (size_t)tileM * 128 * KDIM;
    const __nv_bfloat16* Abl = Al + (size_t)tileM * 128 * KDIM;
    const __nv_bfloat16* Bbh = Bh + (size_t)tileN * 256 * KDIM;
    const __nv_bfloat16* Bbl = Bl + (size_t)tileN * 256 * KDIM;

    const uint32_t aRC = (uint32_t)((wm * 64 + (sel & 1) * 8 + l8) * TROW + (sel >> 1) * 8) * 2;
    const uint32_t bRC = (uint32_t)((wn * 32 + (sel >> 1) * 8 + l8) * TROW + (sel & 1) * 8) * 2;
    const uint32_t aAH = smem0 + OFF_GA_H + aRC;
    const uint32_t aAL = smem0 + OFF_GA_L + aRC;
    const uint32_t bAH = smem0 + OFF_GB_H + bRC;
    const uint32_t bAL = smem0 + OFF_GB_L + bRC;

    float acc[4][4][4];
#pragma unroll
    for (int i = 0; i < 4; i++)
#pragma unroll
        for (int j = 0; j < 4; j++)
#pragma unroll
            for (int r = 0; r < 4; r++) acc[i][j][r] = 0.0f;

    auto issue = [&](int s, int buf) {
        const int k0 = s * GBK;
        const uint32_t base = smem0 + buf * STAGE_BYTES;
        // A tiles: 128 rows x 4 chunks = 512 transfers -> 1 per thread
        {
            int row = tid >> 2, ch = tid & 3;
            uint32_t soff = (uint32_t)(row * TROW + ch * 8) * 2;
            size_t goff = (size_t)row * KDIM + k0 + ch * 8;
            cp_async16(base + OFF_GA_H + soff, Abh + goff);
            cp_async16(base + OFF_GA_L + soff, Abl + goff);
        }
        // B tiles: 256 rows x 4 chunks = 1024 transfers -> 2 per thread
#pragma unroll
        for (int rep = 0; rep < 2; rep++) {
            int c = tid + rep * 512;
            int row = c >> 2, ch = c & 3;
            uint32_t soff = (uint32_t)(row * TROW + ch * 8) * 2;
            size_t goff = (size_t)row * KDIM + k0 + ch * 8;
            cp_async16(base + OFF_GB_H + soff, Bbh + goff);
            cp_async16(base + OFF_GB_L + soff, Bbl + goff);
        }
        cp_commit();
    };

    issue(0, 0);

    int buf = 0;
    for (int s = 0; s < NST; s++) {
        cp_wait0();
        __syncthreads();
        if (s + 1 < NST) issue(s + 1, buf ^ 1);

        const uint32_t bo = (uint32_t)buf * STAGE_BYTES;
#pragma unroll
        for (int k16 = 0; k16 < 2; k16++) {
            const uint32_t kk2 = (uint32_t)(k16 * 16) * 2;
            uint32_t bh[4][2], bl[4][2];
#pragma unroll
            for (int jp = 0; jp < 2; jp++) {
                const uint32_t jo = (uint32_t)(jp * 16 * TROW) * 2 + kk2;
                uint32_t t0, t1, t2, t3;
                ldsm_x4(t0, t1, t2, t3, bAH + jo + bo);
                bh[2 * jp][0] = t0; bh[2 * jp][1] = t1;
                bh[2 * jp + 1][0] = t2; bh[2 * jp + 1][1] = t3;
                ldsm_x4(t0, t1, t2, t3, bAL + jo + bo);
                bl[2 * jp][0] = t0; bl[2 * jp][1] = t1;
                bl[2 * jp + 1][0] = t2; bl[2 * jp + 1][1] = t3;
            }
#pragma unroll
            for (int ip = 0; ip < 2; ip++) {
                uint32_t ah[2][4], al[2][4];
#pragma unroll
                for (int ii = 0; ii < 2; ii++) {
                    const uint32_t io = (uint32_t)((2 * ip + ii) * 16 * TROW) * 2 + kk2;
                    ldsm_x4(ah[ii][0], ah[ii][1], ah[ii][2], ah[ii][3], aAH + io + bo);
                    ldsm_x4(al[ii][0], al[ii][1], al[ii][2], al[ii][3], aAL + io + bo);
                }
#pragma unroll
                for (int ii = 0; ii < 2; ii++)
#pragma unroll
                    for (int j = 0; j < 4; j++)
                        mma_bf16(acc[2 * ip + ii][j],
                                 al[ii][0], al[ii][1], al[ii][2], al[ii][3],
                                 bh[j][0], bh[j][1]);
#pragma unroll
                for (int ii = 0; ii < 2; ii++)
#pragma unroll
                    for (int j = 0; j < 4; j++)
                        mma_bf16(acc[2 * ip + ii][j],
                                 ah[ii][0], ah[ii][1], ah[ii][2], ah[ii][3],
                                 bl[j][0], bl[j][1]);
#pragma unroll
                for (int ii = 0; ii < 2; ii++)
#pragma unroll
                    for (int j = 0; j < 4; j++)
                        mma_bf16(acc[2 * ip + ii][j],
                                 ah[ii][0], ah[ii][1], ah[ii][2], ah[ii][3],
                                 bh[j][0], bh[j][1]);
            }
        }
        buf ^= 1;
    }

#pragma unroll
    for (int i = 0; i < 4; i++) {
        const int row = tileM * 128 + wm * 64 + i * 16 + g;
#pragma unroll
        for (int j = 0; j < 4; j++) {
            const int col = tileN * 256 + wn * 32 + j * 8 + 2 * tig;
            const float b0 = bias[col], b1 = bias[col + 1];
            float v0 = acc[i][j][0] + b0, v1 = acc[i][j][1] + b1;
            float v2 = acc[i][j][2] + b0, v3 = acc[i][j][3] + b1;
            if (Cf) {
                *(float2*)(Cf + (size_t)row * Nt + col) = make_float2(v0, v1);
                *(float2*)(Cf + (size_t)(row + 8) * Nt + col) = make_float2(v2, v3);
            } else {
                __nv_bfloat16 h[2], l[2];
                split_bf16(v0, h[0], l[0]); split_bf16(v1, h[1], l[1]);
                *(ushort2*)(Ch + (size_t)row * Nt + col) = *(ushort2*)h;
                *(ushort2*)(Cl + (size_t)row * Nt + col) = *(ushort2*)l;
                split_bf16(v2, h[0], l[0]); split_bf16(v3, h[1], l[1]);
                *(ushort2*)(Ch + (size_t)(row + 8) * Nt + col) = *(ushort2*)h;
                *(ushort2*)(Cl + (size_t)(row + 8) * Nt + col) = *(ushort2*)l;
            }
        }
    }
}

// ---------------------------------------------------------------------------
// Flash attention, bf16x3, register softmax (unchanged from R9 pass)
// ---------------------------------------------------------------------------
#define QK_STR 72
#define NKT    (SEQ / 64)

#define OFF_QH  0
#define OFF_QL  (OFF_QH + 64 * QK_STR)
#define OFF_KH  (OFF_QL + 64 * QK_STR)
#define OFF_KL  (OFF_KH + 64 * QK_STR)
#define OFF_VH  (OFF_KL + 64 * QK_STR)
#define OFF_VL  (OFF_VH + 64 * QK_STR)
#define OFF_F32 (OFF_VL + 64 * QK_STR)
#define ST_STR  66
#define ST_F    0
#define MS_F    (ST_F + 64 * ST_STR)
#define LS_F    (MS_F + 64)
#define RS_F    (LS_F + 64)
#define RED_F   (RS_F + 64)
#define AT_SMEM_BYTES (OFF_F32 * 2 + (RED_F + 128) * 4)

__global__ __launch_bounds__(256, 2) void attn_kernel() {
    extern __shared__ __nv_bfloat16 smraw[];
    float* fb  = (float*)(smraw + OFF_F32);
    float* sSt = fb + ST_F;
    float* m_s = fb + MS_F;
    float* l_s = fb + LS_F;
    float* rsc = fb + RS_F;
    float* red = fb + RED_F;

    const uint32_t smemU = (uint32_t)__cvta_generic_to_shared(smraw);

    const int tid = threadIdx.x;
    const int wid = tid >> 5;
    const int lane = tid & 31;
    const int g = lane >> 2;
    const int tig = lane & 3;
    const int l8 = lane & 7;
    const int sel = lane >> 3;
    const int wm = wid & 3;
    const int wn = wid >> 2;
    const int m0 = wm * 16;
    const int n0 = wn * 32;

    const int qt = blockIdx.x, h = blockIdx.y, b = blockIdx.z;
    const int q0 = qt * 64;
    const int hoff = h * HD;
    const size_t rowBase = (size_t)b * SEQ;

    const int qlo = q0 / GRID_SZ, qhi = (q0 + 63) / GRID_SZ;
    int ktlo = 0, kthi = NKT - 1;
    while (ktlo < NKT && (64 * ktlo + 63) / GRID_SZ < qlo - MASK_D) ktlo++;
    while (kthi >= 0 && (64 * kthi) / GRID_SZ > qhi + MASK_D) kthi--;

    const uint32_t qRC = (uint32_t)((m0 + (sel & 1) * 8 + l8) * QK_STR + (sel >> 1) * 8) * 2;
    const uint32_t kRC = (uint32_t)((n0 + (sel >> 1) * 8 + l8) * QK_STR + (sel & 1) * 8) * 2;
    const uint32_t qAH = smemU + OFF_QH * 2 + qRC;
    const uint32_t qAL = smemU + OFF_QL * 2 + qRC;
    const uint32_t kAH = smemU + OFF_KH * 2 + kRC;
    const uint32_t kAL = smemU + OFF_KL * 2 + kRC;

    {
#pragma unroll
        for (int rep = 0; rep < 2; rep++) {
            int c = tid + rep * 256;
            int row = c >> 3, ch = c & 7;
            uint32_t soff = (uint32_t)(row * QK_STR + ch * 8) * 2;
            size_t gq = (rowBase + q0 + row) * QKV_COLS + hoff + ch * 8;
            size_t gk = (rowBase + ktlo * 64 + row) * QKV_COLS + CDIM + hoff + ch * 8;
            cp_async16(smemU + OFF_QH * 2 + soff, g_qkvh + gq);
            cp_async16(smemU + OFF_QL * 2 + soff, g_qkvl + gq);
            cp_async16(smemU + OFF_KH * 2 + soff, g_qkvh + gk);
            cp_async16(smemU + OFF_KL * 2 + soff, g_qkvl + gk);
        }
        cp_commit();
    }
    if (tid < 64) { m_s[tid] = -1e30f; l_s[tid] = 0.0f; }

    float accO[8][4];
#pragma unroll
    for (int j = 0; j < 8; j++)
#pragma unroll
        for (int r = 0; r < 4; r++) accO[j][r] = 0.0f;

    for (int kt = ktlo; kt <= kthi; kt++) {
        const int k0 = kt * 64;
        cp_wait0();
        __syncthreads();

        float2 bm0[4], bm1[4];
        {
            const float* bmA = g_bm + ((size_t)h * SEQ + (q0 + m0 + g)) * SEQ + k0 + n0 + 2 * tig;
            const float* bmB = bmA + 8 * SEQ;
#pragma unroll
            for (int j = 0; j < 4; j++) {
                bm0[j] = *(const float2*)(bmA + j * 8);
                bm1[j] = *(const float2*)(bmB + j * 8);
            }
        }

        float sacc[4][4];
#pragma unroll
        for (int j = 0; j < 4; j++)
#pragma unroll
            for (int r = 0; r < 4; r++) sacc[j][r] = 0.0f;

#pragma unroll
        for (int kk4 = 0; kk4 < 4; kk4++) {
            const uint32_t kk2 = (uint32_t)(kk4 * 16) * 2;
            uint32_t qh0, qh1, qh2, qh3, ql0, ql1, ql2, ql3;
            ldsm_x4(qh0, qh1, qh2, qh3, qAH + kk2);
            ldsm_x4(ql0, ql1, ql2, ql3, qAL + kk2);
            uint32_t kh[4][2], kl[4][2];
#pragma unroll
            for (int jp = 0; jp < 2; jp++) {
                const uint32_t jo = (uint32_t)(jp * 16 * QK_STR) * 2 + kk2;
                uint32_t t0, t1, t2, t3;
                ldsm_x4(t0, t1, t2, t3, kAH + jo);
                kh[2 * jp][0] = t0; kh[2 * jp][1] = t1;
                kh[2 * jp + 1][0] = t2; kh[2 * jp + 1][1] = t3;
                ldsm_x4(t0, t1, t2, t3, kAL + jo);
                kl[2 * jp][0] = t0; kl[2 * jp][1] = t1;
                kl[2 * jp + 1][0] = t2; kl[2 * jp + 1][1] = t3;
            }
#pragma unroll
            for (int j = 0; j < 4; j++)
                mma_bf16(sacc[j], ql0, ql1, ql2, ql3, kh[j][0], kh[j][1]);
#pragma unroll
            for (int j = 0; j < 4; j++)
                mma_bf16(sacc[j], qh0, qh1, qh2, qh3, kl[j][0], kl[j][1]);
#pragma unroll
            for (int j = 0; j < 4; j++)
                mma_bf16(sacc[j], qh0, qh1, qh2, qh3, kh[j][0], kh[j][1]);
        }

        float pm0 = -1e30f, pm1 = -1e30f;
#pragma unroll
        for (int j = 0; j < 4; j++) {
            sacc[j][0] = fmaf(sacc[j][0], SOFT_SCALE, bm0[j].x);
            sacc[j][1] = fmaf(sacc[j][1], SOFT_SCALE, bm0[j].y);
            sacc[j][2] = fmaf(sacc[j][2], SOFT_SCALE, bm1[j].x);
            sacc[j][3] = fmaf(sacc[j][3], SOFT_SCALE, bm1[j].y);
            pm0 = fmaxf(pm0, fmaxf(sacc[j][0], sacc[j][1]));
            pm1 = fmaxf(pm1, fmaxf(sacc[j][2], sacc[j][3]));
        }
        pm0 = fmaxf(pm0, __shfl_xor_sync(0xffffffffu, pm0, 1));
        pm0 = fmaxf(pm0, __shfl_xor_sync(0xffffffffu, pm0, 2));
        pm1 = fmaxf(pm1, __shfl_xor_sync(0xffffffffu, pm1, 1));
        pm1 = fmaxf(pm1, __shfl_xor_sync(0xffffffffu, pm1, 2));
        if (tig == 0) {
            red[wn * 64 + m0 + g] = pm0;
            red[wn * 64 + m0 + 8 + g] = pm1;
        }
        __syncthreads();

        {
#pragma unroll
            for (int rep = 0; rep < 2; rep++) {
                int c = tid + rep * 256;
                int row = c >> 3, ch = c & 7;
                uint32_t soff = (uint32_t)(row * QK_STR + ch * 8) * 2;
                size_t gv = (rowBase + k0 + row) * QKV_COLS + 2 * CDIM + hoff + ch * 8;
                cp_async16(smemU + OFF_VH * 2 + soff, g_qkvh + gv);
                cp_async16(smemU + OFF_VL * 2 + soff, g_qkvl + gv);
            }
            cp_commit();
            if (kt < kthi) {
#pragma unroll
                for (int rep = 0; rep < 2; rep++) {
                    int c = tid + rep * 256;
                    int row = c >> 3, ch = c & 7;
                    uint32_t soff = (uint32_t)(row * QK_STR + ch * 8) * 2;
                    size_t gk = (rowBase + k0 + 64 + row) * QKV_COLS + CDIM + hoff + ch * 8;
                    cp_async16(smemU + OFF_KH * 2 + soff, g_qkvh + gk);
                    cp_async16(smemU + OFF_KL * 2 + soff, g_qkvl + gk);
                }
            }
            cp_commit();
        }

        if (tid < 64) {
            int r = tid;
            float mn = fmaxf(m_s[r], fmaxf(red[r], red[64 + r]));
            rsc[r] = __expf(m_s[r] - mn);
            m_s[r] = mn;
        }
        __syncthreads();

        uint32_t pa_h[2][4], pa_l[2][4];
        float ps0 = 0.0f, ps1 = 0.0f;
        {
            float mr0 = m_s[m0 + g];
            float mr1 = m_s[m0 + 8 + g];
#pragma unroll
            for (int j = 0; j < 4; j++) {
                float e0 = __expf(sacc[j][0] - mr0);
                float e1 = __expf(sacc[j][1] - mr0);
                float e2 = __expf(sacc[j][2] - mr1);
                float e3 = __expf(sacc[j][3] - mr1);
                ps0 += e0 + e1;
                ps1 += e2 + e3;
                float h0 = __bfloat162float(__float2bfloat16(e0));
                float h1 = __bfloat162float(__float2bfloat16(e1));
                float h2 = __bfloat162float(__float2bfloat16(e2));
                float h3 = __bfloat162float(__float2bfloat16(e3));
                const int c = j >> 1;
                const int hi2 = (j & 1) * 2;
                pa_h[c][hi2]     = pack2(h0, h1);
                pa_h[c][hi2 + 1] = pack2(h2, h3);
                pa_l[c][hi2]     = pack2(e0 - h0, e1 - h1);
                pa_l[c][hi2 + 1] = pack2(e2 - h2, e3 - h3);
            }
        }
        ps0 += __shfl_xor_sync(0xffffffffu, ps0, 1);
        ps0 += __shfl_xor_sync(0xffffffffu, ps0, 2);
        ps1 += __shfl_xor_sync(0xffffffffu, ps1, 1);
        ps1 += __shfl_xor_sync(0xffffffffu, ps1, 2);
        if (tig == 0) {
            red[wn * 64 + m0 + g] = ps0;
            red[wn * 64 + m0 + 8 + g] = ps1;
        }
        __syncthreads();
        if (tid < 64) {
            int r = tid;
            l_s[r] = l_s[r] * rsc[r] + red[r] + red[64 + r];
        }

        cp_wait1();
        __syncthreads();

        {
            float r0 = rsc[m0 + g], r1 = rsc[m0 + 8 + g];
#pragma unroll
            for (int j = 0; j < 8; j++) {
                accO[j][0] *= r0; accO[j][1] *= r0;
                accO[j][2] *= r1; accO[j][3] *= r1;
            }
        }
        {
            const int quad = lane >> 3, lrow = lane & 7;
            const int ksub = (quad & 1) * 8;
            const int csel = (quad >> 1) * 8;
#pragma unroll
            for (int c = 0; c < 2; c++) {
                const int krow = n0 + c * 16 + ksub + lrow;
                uint32_t vh[4][4], vl[4][4];
#pragma unroll
                for (int jp = 0; jp < 4; jp++) {
                    uint32_t vrow = (uint32_t)(krow * QK_STR + jp * 16 + csel) * 2;
                    ldsm_x4_t(vh[jp][0], vh[jp][1], vh[jp][2], vh[jp][3],
                              smemU + OFF_VH * 2 + vrow);
                    ldsm_x4_t(vl[jp][0], vl[jp][1], vl[jp][2], vl[jp][3],
                              smemU + OFF_VL * 2 + vrow);
                }
#pragma unroll
                for (int jp = 0; jp < 4; jp++) {
                    mma_bf16(accO[jp * 2],     pa_l[c][0], pa_l[c][1], pa_l[c][2], pa_l[c][3],
                             vh[jp][0], vh[jp][1]);
                    mma_bf16(accO[jp * 2 + 1], pa_l[c][0], pa_l[c][1], pa_l[c][2], pa_l[c][3],
                             vh[jp][2], vh[jp][3]);
                }
#pragma unroll
                for (int jp = 0; jp < 4; jp++) {
                    mma_bf16(accO[jp * 2],     pa_h[c][0], pa_h[c][1], pa_h[c][2], pa_h[c][3],
                             vl[jp][0], vl[jp][1]);
                    mma_bf16(accO[jp * 2 + 1], pa_h[c][0], pa_h[c][1], pa_h[c][2], pa_h[c][3],
                             vl[jp][2], vl[jp][3]);
                }
#pragma unroll
                for (int jp = 0; jp < 4; jp++) {
                    mma_bf16(accO[jp * 2],     pa_h[c][0], pa_h[c][1], pa_h[c][2], pa_h[c][3],
                             vh[jp][0], vh[jp][1]);
                    mma_bf16(accO[jp * 2 + 1], pa_h[c][0], pa_h[c][1], pa_h[c][2], pa_h[c][3],
                             vh[jp][2], vh[jp][3]);
                }
            }
        }
    }

    __syncthreads();

    if (wn == 1) {
#pragma unroll
        for (int j = 0; j < 8; j++) {
            *(float2*)(sSt + (m0 + g) * ST_STR + j * 8 + 2 * tig) =
                make_float2(accO[j][0], accO[j][1]);
            *(float2*)(sSt + (m0 + 8 + g) * ST_STR + j * 8 + 2 * tig) =
                make_float2(accO[j][2], accO[j][3]);
        }
    }
    __syncthreads();
    if (wn == 0) {
        float inv0 = 1.0f / l_s[m0 + g];
        float inv1 = 1.0f / l_s[m0 + 8 + g];
#pragma unroll
        for (int j = 0; j < 8; j++) {
            float2 o0 = *(const float2*)(sSt + (m0 + g) * ST_STR + j * 8 + 2 * tig);
            float2 o1 = *(const float2*)(sSt + (m0 + 8 + g) * ST_STR + j * 8 + 2 * tig);
            float v0 = (accO[j][0] + o0.x) * inv0;
            float v1 = (accO[j][1] + o0.y) * inv0;
            float v2 = (accO[j][2] + o1.x) * inv1;
            float v3 = (accO[j][3] + o1.y) * inv1;
            int col = hoff + j * 8 + 2 * tig;
            size_t a0 = (rowBase + q0 + m0 + g) * CDIM + col;
            size_t a1 = (rowBase + q0 + m0 + 8 + g) * CDIM + col;
            __nv_bfloat16 hh[2], ll[2];
            split_bf16(v0, hh[0], ll[0]); split_bf16(v1, hh[1], ll[1]);
            *(ushort2*)(g_x2h + a0) = *(ushort2*)hh;
            *(ushort2*)(g_x2l + a0) = *(ushort2*)ll;
            split_bf16(v2, hh[0], ll[0]); split_bf16(v3, hh[1], ll[1]);
            *(ushort2*)(g_x2h + a1) = *(ushort2*)hh;
            *(ushort2*)(g_x2l + a1) = *(ushort2*)ll;
        }
    }
}

// ---------------------------------------------------------------------------
// Launch
// ---------------------------------------------------------------------------
extern "C" void kernel_launch(void* const* d_in, const int* in_sizes, int n_in,
                              void* d_out, int out_size) {
    const float* x         = (const float*)d_in[0];
    const float* w_qkv     = (const float*)d_in[1];
    const float* b_qkv     = (const float*)d_in[2];
    const float* rel_table = (const float*)d_in[3];
    const float* w_proj    = (const float*)d_in[4];
    const float* b_proj    = (const float*)d_in[5];
    float* out = (float*)d_out;

    __nv_bfloat16 *pqh, *pql, *pxh, *pxl, *px2h, *px2l, *pwqh, *pwql, *pwph, *pwpl;
    cudaGetSymbolAddress((void**)&pqh, g_qkvh);
    cudaGetSymbolAddress((void**)&pql, g_qkvl);
    cudaGetSymbolAddress((void**)&pxh, g_xh);
    cudaGetSymbolAddress((void**)&pxl, g_xl);
    cudaGetSymbolAddress((void**)&px2h, g_x2h);
    cudaGetSymbolAddress((void**)&px2l, g_x2l);
    cudaGetSymbolAddress((void**)&pwqh, g_wqkvTh);
    cudaGetSymbolAddress((void**)&pwql, g_wqkvTl);
    cudaGetSymbolAddress((void**)&pwph, g_wprojTh);
    cudaGetSymbolAddress((void**)&pwpl, g_wprojTl);

    cudaFuncSetAttribute(attn_kernel, cudaFuncAttributeMaxDynamicSharedMemorySize,
                         AT_SMEM_BYTES);
    cudaFuncSetAttribute(gemm_bf16x3, cudaFuncAttributeMaxDynamicSharedMemorySize,
                         G_SMEM_BYTES);

    const int N4 = MROWS * CDIM / 4;

    // 0) prepasses
    split_kernel<<<(N4 + 255) / 256, 256>>>(x, pxh, pxl, N4);
    transpose_split_kernel<<<dim3(QKV_COLS / 32, CDIM / 32), dim3(32, 8)>>>(
        w_qkv, pwqh, pwql, CDIM, QKV_COLS);
    transpose_split_kernel<<<dim3(CDIM / 32, CDIM / 32), dim3(32, 8)>>>(
        w_proj, pwph, pwpl, CDIM, CDIM);

    // 1) QKV projection -> hi/lo bf16 output   (launch #4: ncu target)
    gemm_bf16x3<<<dim3(QKV_COLS / 256, MROWS / 128), 512, G_SMEM_BYTES>>>(
        pxh, pxl, pwqh, pwql, b_qkv, nullptr, pqh, pql, QKV_COLS);

    // 2) bias+mask precompute
    biasmask_kernel<<<(HEADS * SEQ * SEQ + 255) / 256, 256>>>(rel_table);

    // 3) attention -> hi/lo split output
    attn_kernel<<<dim3(SEQ / 64, HEADS, BATCH), 256, AT_SMEM_BYTES>>>();

    // 4) output projection -> fp32 out
    gemm_bf16x3<<<dim3(CDIM / 256, MROWS / 128), 512, G_SMEM_BYTES>>>(
        px2h, px2l, pwph, pwpl, b_proj, out, nullptr, nullptr, CDIM);
}

// round 12
// speedup vs baseline: 1.0924x; 1.0924x over previous
#include <cuda_runtime.h>
#include <cuda_bf16.h>
#include <cstdint>

// ---------------------------------------------------------------------------
// Problem dimensions (fixed by the reference)
// ---------------------------------------------------------------------------
#define BATCH     32
#define HEADS     12
#define SEQ       576
#define HD        64
#define CDIM      768
#define MROWS     (BATCH * SEQ)      // 18432
#define QKV_COLS  (3 * CDIM)         // 2304
#define GRID_SZ   24
#define MSIZE     47
#define MASK_D    12
#define SOFT_SCALE 0.125f

// ---------------------------------------------------------------------------
// Scratch (device globals)
// ---------------------------------------------------------------------------
__device__ float g_bm[(size_t)HEADS * SEQ * SEQ];                 // 16 MB
__device__ __nv_bfloat16 g_qkvh[(size_t)MROWS * QKV_COLS];
__device__ __nv_bfloat16 g_qkvl[(size_t)MROWS * QKV_COLS];
__device__ __nv_bfloat16 g_xh[(size_t)MROWS * CDIM];
__device__ __nv_bfloat16 g_xl[(size_t)MROWS * CDIM];
__device__ __nv_bfloat16 g_x2h[(size_t)MROWS * CDIM];
__device__ __nv_bfloat16 g_x2l[(size_t)MROWS * CDIM];
__device__ __nv_bfloat16 g_wqkvTh[(size_t)QKV_COLS * CDIM];
__device__ __nv_bfloat16 g_wqkvTl[(size_t)QKV_COLS * CDIM];
__device__ __nv_bfloat16 g_wprojTh[(size_t)CDIM * CDIM];
__device__ __nv_bfloat16 g_wprojTl[(size_t)CDIM * CDIM];

// ---------------------------------------------------------------------------
// Helpers
// ---------------------------------------------------------------------------
__device__ __forceinline__ void cp_async16(uint32_t smem_dst, const void* gptr) {
    asm volatile("cp.async.cg.shared.global [%0], [%1], 16;"
                 :: "r"(smem_dst), "l"(gptr));
}
__device__ __forceinline__ void cp_commit() { asm volatile("cp.async.commit_group;"); }
__device__ __forceinline__ void cp_wait0()  { asm volatile("cp.async.wait_group 0;"); }
__device__ __forceinline__ void cp_wait1()  { asm volatile("cp.async.wait_group 1;"); }

__device__ __forceinline__ void mma_bf16(
    float* c, uint32_t a0, uint32_t a1, uint32_t a2, uint32_t a3,
    uint32_t b0, uint32_t b1)
{
    asm volatile(
        "mma.sync.aligned.m16n8k16.row.col.f32.bf16.bf16.f32 "
        "{%0,%1,%2,%3}, {%4,%5,%6,%7}, {%8,%9}, {%0,%1,%2,%3};"
        : "+f"(c[0]), "+f"(c[1]), "+f"(c[2]), "+f"(c[3])
        : "r"(a0), "r"(a1), "r"(a2), "r"(a3), "r"(b0), "r"(b1));
}

__device__ __forceinline__ void ldsm_x4(uint32_t& r0, uint32_t& r1,
                                        uint32_t& r2, uint32_t& r3,
                                        uint32_t addr) {
    asm volatile("ldmatrix.sync.aligned.m8n8.x4.shared.b16 {%0,%1,%2,%3}, [%4];"
                 : "=r"(r0), "=r"(r1), "=r"(r2), "=r"(r3) : "r"(addr));
}
__device__ __forceinline__ void ldsm_x4_t(uint32_t& r0, uint32_t& r1,
                                          uint32_t& r2, uint32_t& r3,
                                          uint32_t addr) {
    asm volatile("ldmatrix.sync.aligned.m8n8.x4.trans.shared.b16 {%0,%1,%2,%3}, [%4];"
                 : "=r"(r0), "=r"(r1), "=r"(r2), "=r"(r3) : "r"(addr));
}

__device__ __forceinline__ void split_bf16(float v, __nv_bfloat16& h, __nv_bfloat16& l) {
    h = __float2bfloat16(v);
    l = __float2bfloat16(v - __bfloat162float(h));
}
__device__ __forceinline__ uint32_t pack2(float a, float b) {
    __nv_bfloat162 t = __floats2bfloat162_rn(a, b);
    return *(uint32_t*)&t;
}

// ---------------------------------------------------------------------------
// Prepass kernels
// ---------------------------------------------------------------------------
__global__ void split_kernel(const float* __restrict__ in,
                             __nv_bfloat16* __restrict__ hi,
                             __nv_bfloat16* __restrict__ lo, int n4) {
    int t = blockIdx.x * 256 + threadIdx.x;
    if (t >= n4) return;
    float4 v = *(const float4*)(in + (size_t)t * 4);
    __nv_bfloat16 h[4], l[4];
    split_bf16(v.x, h[0], l[0]);
    split_bf16(v.y, h[1], l[1]);
    split_bf16(v.z, h[2], l[2]);
    split_bf16(v.w, h[3], l[3]);
    *(ushort4*)(hi + (size_t)t * 4) = *(ushort4*)h;
    *(ushort4*)(lo + (size_t)t * 4) = *(ushort4*)l;
}

__global__ void transpose_split_kernel(const float* __restrict__ src,
                                       __nv_bfloat16* __restrict__ dstH,
                                       __nv_bfloat16* __restrict__ dstL,
                                       int R, int C) {
    __shared__ float t[32][33];
    int bx = blockIdx.x * 32, by = blockIdx.y * 32;
#pragma unroll
    for (int i = 0; i < 32; i += 8)
        t[threadIdx.y + i][threadIdx.x] =
            src[(size_t)(by + threadIdx.y + i) * C + bx + threadIdx.x];
    __syncthreads();
#pragma unroll
    for (int i = 0; i < 32; i += 8) {
        float v = t[threadIdx.x][threadIdx.y + i];
        __nv_bfloat16 h, l;
        split_bf16(v, h, l);
        size_t o = (size_t)(bx + threadIdx.y + i) * R + by + threadIdx.x;
        dstH[o] = h;
        dstL[o] = l;
    }
}

__global__ void biasmask_kernel(const float* __restrict__ rel_table) {
    int t = blockIdx.x * 256 + threadIdx.x;
    if (t >= HEADS * SEQ * SEQ) return;
    int h = t / (SEQ * SEQ);
    int r = t - h * (SEQ * SEQ);
    int q = r / SEQ;
    int k = r - q * SEQ;
    int qr = q / GRID_SZ, qc = q - qr * GRID_SZ;
    int kr = k / GRID_SZ, kc = k - kr * GRID_SZ;
    int dr = kr - qr, dc = kc - qc;
    int idx = (dr + GRID_SZ - 1) * MSIZE + (dc + GRID_SZ - 1);
    float v = rel_table[idx * HEADS + h];
    int cheb = max(abs(dr), abs(dc));
    if (cheb > MASK_D) v += -100.0f;
    g_bm[t] = v;
}

// ---------------------------------------------------------------------------
// bf16x3 tensor-core GEMM — R9 config (128x128, 256 thr, 2 CTA/SM; best known)
// ---------------------------------------------------------------------------
#define KDIM 768
#define GBK  32
#define NST  (KDIM / GBK)
#define TROW 40
#define TILE_BYTES (128 * TROW * 2)
#define STAGE_BYTES (4 * TILE_BYTES)
#define G_SMEM_BYTES (2 * STAGE_BYTES)

__global__ __launch_bounds__(256, 2)
void gemm_bf16x3(const __nv_bfloat16* __restrict__ Ah,
                 const __nv_bfloat16* __restrict__ Al,
                 const __nv_bfloat16* __restrict__ Bh,
                 const __nv_bfloat16* __restrict__ Bl,
                 const float* __restrict__ bias,
                 float* __restrict__ Cf,
                 __nv_bfloat16* __restrict__ Ch,
                 __nv_bfloat16* __restrict__ Cl, int Nt) {
    extern __shared__ __nv_bfloat16 smb[];
    const uint32_t smem0 = (uint32_t)__cvta_generic_to_shared(smb);

    const int tid = threadIdx.x;
    const int wid = tid >> 5;
    const int lane = tid & 31;
    const int g = lane >> 2;
    const int tig = lane & 3;
    const int l8 = lane & 7;
    const int sel = lane >> 3;
    const int wm = wid & 1;
    const int wn = wid >> 1;
    const int tileM = blockIdx.y, tileN = blockIdx.x;

    const __nv_bfloat16* Abh = Ah + (size_t)tileM * 128 * KDIM;
    const __nv_bfloat16* Abl = Al + (size_t)tileM * 128 * KDIM;
    const __nv_bfloat16* Bbh = Bh + (size_t)tileN * 128 * KDIM;
    const __nv_bfloat16* Bbl = Bl + (size_t)tileN * 128 * KDIM;

    const uint32_t aRC = (uint32_t)((wm * 64 + (sel & 1) * 8 + l8) * TROW + (sel >> 1) * 8) * 2;
    const uint32_t bRC = (uint32_t)((wn * 32 + (sel >> 1) * 8 + l8) * TROW + (sel & 1) * 8) * 2;
    const uint32_t aAH = smem0 + 0 * TILE_BYTES + aRC;
    const uint32_t aAL = smem0 + 1 * TILE_BYTES + aRC;
    const uint32_t bAH = smem0 + 2 * TILE_BYTES + bRC;
    const uint32_t bAL = smem0 + 3 * TILE_BYTES + bRC;

    float acc[4][4][4];
#pragma unroll
    for (int i = 0; i < 4; i++)
#pragma unroll
        for (int j = 0; j < 4; j++)
#pragma unroll
            for (int r = 0; r < 4; r++) acc[i][j][r] = 0.0f;

    auto issue = [&](int s, int buf) {
        const int k0 = s * GBK;
        const uint32_t base = smem0 + buf * STAGE_BYTES;
#pragma unroll
        for (int rep = 0; rep < 2; rep++) {
            int c = tid + rep * 256;
            int row = c >> 2, ch = c & 3;
            uint32_t soff = (uint32_t)(row * TROW + ch * 8) * 2;
            size_t goff = (size_t)row * KDIM + k0 + ch * 8;
            cp_async16(base + 0 * TILE_BYTES + soff, Abh + goff);
            cp_async16(base + 1 * TILE_BYTES + soff, Abl + goff);
            cp_async16(base + 2 * TILE_BYTES + soff, Bbh + goff);
            cp_async16(base + 3 * TILE_BYTES + soff, Bbl + goff);
        }
        cp_commit();
    };

    issue(0, 0);

    int buf = 0;
    for (int s = 0; s < NST; s++) {
        cp_wait0();
        __syncthreads();
        if (s + 1 < NST) issue(s + 1, buf ^ 1);

        const uint32_t bo = (uint32_t)buf * STAGE_BYTES;
#pragma unroll
        for (int k16 = 0; k16 < 2; k16++) {
            const uint32_t kk2 = (uint32_t)(k16 * 16) * 2;
            uint32_t bh[4][2], bl[4][2];
#pragma unroll
            for (int jp = 0; jp < 2; jp++) {
                const uint32_t jo = (uint32_t)(jp * 16 * TROW) * 2 + kk2;
                uint32_t t0, t1, t2, t3;
                ldsm_x4(t0, t1, t2, t3, bAH + jo + bo);
                bh[2 * jp][0] = t0; bh[2 * jp][1] = t1;
                bh[2 * jp + 1][0] = t2; bh[2 * jp + 1][1] = t3;
                ldsm_x4(t0, t1, t2, t3, bAL + jo + bo);
                bl[2 * jp][0] = t0; bl[2 * jp][1] = t1;
                bl[2 * jp + 1][0] = t2; bl[2 * jp + 1][1] = t3;
            }
#pragma unroll
            for (int ip = 0; ip < 2; ip++) {
                uint32_t ah[2][4], al[2][4];
#pragma unroll
                for (int ii = 0; ii < 2; ii++) {
                    const uint32_t io = (uint32_t)((2 * ip + ii) * 16 * TROW) * 2 + kk2;
                    ldsm_x4(ah[ii][0], ah[ii][1], ah[ii][2], ah[ii][3], aAH + io + bo);
                    ldsm_x4(al[ii][0], al[ii][1], al[ii][2], al[ii][3], aAL + io + bo);
                }
#pragma unroll
                for (int ii = 0; ii < 2; ii++)
#pragma unroll
                    for (int j = 0; j < 4; j++)
                        mma_bf16(acc[2 * ip + ii][j],
                                 al[ii][0], al[ii][1], al[ii][2], al[ii][3],
                                 bh[j][0], bh[j][1]);
#pragma unroll
                for (int ii = 0; ii < 2; ii++)
#pragma unroll
                    for (int j = 0; j < 4; j++)
                        mma_bf16(acc[2 * ip + ii][j],
                                 ah[ii][0], ah[ii][1], ah[ii][2], ah[ii][3],
                                 bl[j][0], bl[j][1]);
#pragma unroll
                for (int ii = 0; ii < 2; ii++)
#pragma unroll
                    for (int j = 0; j < 4; j++)
                        mma_bf16(acc[2 * ip + ii][j],
                                 ah[ii][0], ah[ii][1], ah[ii][2], ah[ii][3],
                                 bh[j][0], bh[j][1]);
            }
        }
        buf ^= 1;
    }

#pragma unroll
    for (int i = 0; i < 4; i++) {
        const int row = tileM * 128 + wm * 64 + i * 16 + g;
#pragma unroll
        for (int j = 0; j < 4; j++) {
            const int col = tileN * 128 + wn * 32 + j * 8 + 2 * tig;
            const float b0 = bias[col], b1 = bias[col + 1];
            float v0 = acc[i][j][0] + b0, v1 = acc[i][j][1] + b1;
            float v2 = acc[i][j][2] + b0, v3 = acc[i][j][3] + b1;
            if (Cf) {
                *(float2*)(Cf + (size_t)row * Nt + col) = make_float2(v0, v1);
                *(float2*)(Cf + (size_t)(row + 8) * Nt + col) = make_float2(v2, v3);
            } else {
                __nv_bfloat16 h[2], l[2];
                split_bf16(v0, h[0], l[0]); split_bf16(v1, h[1], l[1]);
                *(ushort2*)(Ch + (size_t)row * Nt + col) = *(ushort2*)h;
                *(ushort2*)(Cl + (size_t)row * Nt + col) = *(ushort2*)l;
                split_bf16(v2, h[0], l[0]); split_bf16(v3, h[1], l[1]);
                *(ushort2*)(Ch + (size_t)(row + 8) * Nt + col) = *(ushort2*)h;
                *(ushort2*)(Cl + (size_t)(row + 8) * Nt + col) = *(ushort2*)l;
            }
        }
    }
}

// ---------------------------------------------------------------------------
// Flash attention, bf16x3; per-warp split-KV online softmax (no smem softmax,
// 3 barriers per k-tile). wn halves reconciled exactly once at the end.
// ---------------------------------------------------------------------------
#define QK_STR 72
#define NKT    (SEQ / 64)

#define OFF_QH  0
#define OFF_QL  (OFF_QH + 64 * QK_STR)
#define OFF_KH  (OFF_QL + 64 * QK_STR)
#define OFF_KL  (OFF_KH + 64 * QK_STR)
#define OFF_VH  (OFF_KL + 64 * QK_STR)
#define OFF_VL  (OFF_VH + 64 * QK_STR)
#define OFF_F32 (OFF_VL + 64 * QK_STR)
#define ST_STR  66
#define ST_F    0
#define MW_F    (ST_F + 64 * ST_STR)
#define LW_F    (MW_F + 64)
#define AT_SMEM_BYTES (OFF_F32 * 2 + (LW_F + 64) * 4)

__global__ __launch_bounds__(256, 2) void attn_kernel() {
    extern __shared__ __nv_bfloat16 smraw[];
    float* fb  = (float*)(smraw + OFF_F32);
    float* sSt = fb + ST_F;
    float* mW  = fb + MW_F;
    float* lW  = fb + LW_F;

    const uint32_t smemU = (uint32_t)__cvta_generic_to_shared(smraw);

    const int tid = threadIdx.x;
    const int wid = tid >> 5;
    const int lane = tid & 31;
    const int g = lane >> 2;
    const int tig = lane & 3;
    const int l8 = lane & 7;
    const int sel = lane >> 3;
    const int wm = wid & 3;
    const int wn = wid >> 2;
    const int m0 = wm * 16;
    const int n0 = wn * 32;

    const int qt = blockIdx.x, h = blockIdx.y, b = blockIdx.z;
    const int q0 = qt * 64;
    const int hoff = h * HD;
    const size_t rowBase = (size_t)b * SEQ;

    const int qlo = q0 / GRID_SZ, qhi = (q0 + 63) / GRID_SZ;
    int ktlo = 0, kthi = NKT - 1;
    while (ktlo < NKT && (64 * ktlo + 63) / GRID_SZ < qlo - MASK_D) ktlo++;
    while (kthi >= 0 && (64 * kthi) / GRID_SZ > qhi + MASK_D) kthi--;

    const uint32_t qRC = (uint32_t)((m0 + (sel & 1) * 8 + l8) * QK_STR + (sel >> 1) * 8) * 2;
    const uint32_t kRC = (uint32_t)((n0 + (sel >> 1) * 8 + l8) * QK_STR + (sel & 1) * 8) * 2;
    const uint32_t qAH = smemU + OFF_QH * 2 + qRC;
    const uint32_t qAL = smemU + OFF_QL * 2 + qRC;
    const uint32_t kAH = smemU + OFF_KH * 2 + kRC;
    const uint32_t kAL = smemU + OFF_KL * 2 + kRC;

    // ---- prologue: Q (hi/lo) and K(ktlo)
    {
#pragma unroll
        for (int rep = 0; rep < 2; rep++) {
            int c = tid + rep * 256;
            int row = c >> 3, ch = c & 7;
            uint32_t soff = (uint32_t)(row * QK_STR + ch * 8) * 2;
            size_t gq = (rowBase + q0 + row) * QKV_COLS + hoff + ch * 8;
            size_t gk = (rowBase + ktlo * 64 + row) * QKV_COLS + CDIM + hoff + ch * 8;
            cp_async16(smemU + OFF_QH * 2 + soff, g_qkvh + gq);
            cp_async16(smemU + OFF_QL * 2 + soff, g_qkvl + gq);
            cp_async16(smemU + OFF_KH * 2 + soff, g_qkvh + gk);
            cp_async16(smemU + OFF_KL * 2 + soff, g_qkvl + gk);
        }
        cp_commit();
    }

    // per-warp running softmax state (group-uniform across tig after shfls)
    float m0r = -1e30f, m1r = -1e30f;
    float l0r = 0.0f,   l1r = 0.0f;

    float accO[8][4];
#pragma unroll
    for (int j = 0; j < 8; j++)
#pragma unroll
        for (int r = 0; r < 4; r++) accO[j][r] = 0.0f;

    for (int kt = ktlo; kt <= kthi; kt++) {
        const int k0 = kt * 64;
        cp_wait0();
        __syncthreads();                       // [barrier 1] K(kt)+V(kt-1 life) ready

        float2 bm0[4], bm1[4];
        {
            const float* bmA = g_bm + ((size_t)h * SEQ + (q0 + m0 + g)) * SEQ + k0 + n0 + 2 * tig;
            const float* bmB = bmA + 8 * SEQ;
#pragma unroll
            for (int j = 0; j < 4; j++) {
                bm0[j] = *(const float2*)(bmA + j * 8);
                bm1[j] = *(const float2*)(bmB + j * 8);
            }
        }

        // ---- S = Q @ K^T (bf16x3, pass-separated)
        float sacc[4][4];
#pragma unroll
        for (int j = 0; j < 4; j++)
#pragma unroll
            for (int r = 0; r < 4; r++) sacc[j][r] = 0.0f;

#pragma unroll
        for (int kk4 = 0; kk4 < 4; kk4++) {
            const uint32_t kk2 = (uint32_t)(kk4 * 16) * 2;
            uint32_t qh0, qh1, qh2, qh3, ql0, ql1, ql2, ql3;
            ldsm_x4(qh0, qh1, qh2, qh3, qAH + kk2);
            ldsm_x4(ql0, ql1, ql2, ql3, qAL + kk2);
            uint32_t kh[4][2], kl[4][2];
#pragma unroll
            for (int jp = 0; jp < 2; jp++) {
                const uint32_t jo = (uint32_t)(jp * 16 * QK_STR) * 2 + kk2;
                uint32_t t0, t1, t2, t3;
                ldsm_x4(t0, t1, t2, t3, kAH + jo);
                kh[2 * jp][0] = t0; kh[2 * jp][1] = t1;
                kh[2 * jp + 1][0] = t2; kh[2 * jp + 1][1] = t3;
                ldsm_x4(t0, t1, t2, t3, kAL + jo);
                kl[2 * jp][0] = t0; kl[2 * jp][1] = t1;
                kl[2 * jp + 1][0] = t2; kl[2 * jp + 1][1] = t3;
            }
#pragma unroll
            for (int j = 0; j < 4; j++)
                mma_bf16(sacc[j], ql0, ql1, ql2, ql3, kh[j][0], kh[j][1]);
#pragma unroll
            for (int j = 0; j < 4; j++)
                mma_bf16(sacc[j], qh0, qh1, qh2, qh3, kl[j][0], kl[j][1]);
#pragma unroll
            for (int j = 0; j < 4; j++)
                mma_bf16(sacc[j], qh0, qh1, qh2, qh3, kh[j][0], kh[j][1]);
        }
        __syncthreads();                       // [barrier 2] all warps done reading K

        // ---- prefetch V(kt), then K(kt+1) (overlaps softmax below)
        {
#pragma unroll
            for (int rep = 0; rep < 2; rep++) {
                int c = tid + rep * 256;
                int row = c >> 3, ch = c & 7;
                uint32_t soff = (uint32_t)(row * QK_STR + ch * 8) * 2;
                size_t gv = (rowBase + k0 + row) * QKV_COLS + 2 * CDIM + hoff + ch * 8;
                cp_async16(smemU + OFF_VH * 2 + soff, g_qkvh + gv);
                cp_async16(smemU + OFF_VL * 2 + soff, g_qkvl + gv);
            }
            cp_commit();
            if (kt < kthi) {
#pragma unroll
                for (int rep = 0; rep < 2; rep++) {
                    int c = tid + rep * 256;
                    int row = c >> 3, ch = c & 7;
                    uint32_t soff = (uint32_t)(row * QK_STR + ch * 8) * 2;
                    size_t gk = (rowBase + k0 + 64 + row) * QKV_COLS + CDIM + hoff + ch * 8;
                    cp_async16(smemU + OFF_KH * 2 + soff, g_qkvh + gk);
                    cp_async16(smemU + OFF_KL * 2 + soff, g_qkvl + gk);
                }
            }
            cp_commit();
        }

        // ---- per-warp online softmax (registers + shfl only)
        float pm0 = -1e30f, pm1 = -1e30f;
#pragma unroll
        for (int j = 0; j < 4; j++) {
            sacc[j][0] = fmaf(sacc[j][0], SOFT_SCALE, bm0[j].x);
            sacc[j][1] = fmaf(sacc[j][1], SOFT_SCALE, bm0[j].y);
            sacc[j][2] = fmaf(sacc[j][2], SOFT_SCALE, bm1[j].x);
            sacc[j][3] = fmaf(sacc[j][3], SOFT_SCALE, bm1[j].y);
            pm0 = fmaxf(pm0, fmaxf(sacc[j][0], sacc[j][1]));
            pm1 = fmaxf(pm1, fmaxf(sacc[j][2], sacc[j][3]));
        }
        pm0 = fmaxf(pm0, __shfl_xor_sync(0xffffffffu, pm0, 1));
        pm0 = fmaxf(pm0, __shfl_xor_sync(0xffffffffu, pm0, 2));
        pm1 = fmaxf(pm1, __shfl_xor_sync(0xffffffffu, pm1, 1));
        pm1 = fmaxf(pm1, __shfl_xor_sync(0xffffffffu, pm1, 2));

        float mn0 = fmaxf(m0r, pm0), mn1 = fmaxf(m1r, pm1);
        float sc0 = __expf(m0r - mn0), sc1 = __expf(m1r - mn1);
        m0r = mn0; m1r = mn1;

        uint32_t pa_h[2][4], pa_l[2][4];
        float ps0 = 0.0f, ps1 = 0.0f;
#pragma unroll
        for (int j = 0; j < 4; j++) {
            float e0 = __expf(sacc[j][0] - mn0);
            float e1 = __expf(sacc[j][1] - mn0);
            float e2 = __expf(sacc[j][2] - mn1);
            float e3 = __expf(sacc[j][3] - mn1);
            ps0 += e0 + e1;
            ps1 += e2 + e3;
            float h0 = __bfloat162float(__float2bfloat16(e0));
            float h1 = __bfloat162float(__float2bfloat16(e1));
            float h2 = __bfloat162float(__float2bfloat16(e2));
            float h3 = __bfloat162float(__float2bfloat16(e3));
            const int c = j >> 1;
            const int hi2 = (j & 1) * 2;
            pa_h[c][hi2]     = pack2(h0, h1);
            pa_h[c][hi2 + 1] = pack2(h2, h3);
            pa_l[c][hi2]     = pack2(e0 - h0, e1 - h1);
            pa_l[c][hi2 + 1] = pack2(e2 - h2, e3 - h3);
        }
        ps0 += __shfl_xor_sync(0xffffffffu, ps0, 1);
        ps0 += __shfl_xor_sync(0xffffffffu, ps0, 2);
        ps1 += __shfl_xor_sync(0xffffffffu, ps1, 1);
        ps1 += __shfl_xor_sync(0xffffffffu, ps1, 2);
        l0r = l0r * sc0 + ps0;
        l1r = l1r * sc1 + ps1;

        // ---- rescale O by per-warp factors
#pragma unroll
        for (int j = 0; j < 8; j++) {
            accO[j][0] *= sc0; accO[j][1] *= sc0;
            accO[j][2] *= sc1; accO[j][3] *= sc1;
        }

        cp_wait1();
        __syncthreads();                       // [barrier 3] V(kt) visible

        // ---- O += P @ V (V frags hoisted, 3 passes)
        {
            const int quad = lane >> 3, lrow = lane & 7;
            const int ksub = (quad & 1) * 8;
            const int csel = (quad >> 1) * 8;
#pragma unroll
            for (int c = 0; c < 2; c++) {
                const int krow = n0 + c * 16 + ksub + lrow;
                uint32_t vh[4][4], vl[4][4];
#pragma unroll
                for (int jp = 0; jp < 4; jp++) {
                    uint32_t vrow = (uint32_t)(krow * QK_STR + jp * 16 + csel) * 2;
                    ldsm_x4_t(vh[jp][0], vh[jp][1], vh[jp][2], vh[jp][3],
                              smemU + OFF_VH * 2 + vrow);
                    ldsm_x4_t(vl[jp][0], vl[jp][1], vl[jp][2], vl[jp][3],
                              smemU + OFF_VL * 2 + vrow);
                }
#pragma unroll
                for (int jp = 0; jp < 4; jp++) {
                    mma_bf16(accO[jp * 2],     pa_l[c][0], pa_l[c][1], pa_l[c][2], pa_l[c][3],
                             vh[jp][0], vh[jp][1]);
                    mma_bf16(accO[jp * 2 + 1], pa_l[c][0], pa_l[c][1], pa_l[c][2], pa_l[c][3],
                             vh[jp][2], vh[jp][3]);
                }
#pragma unroll
                for (int jp = 0; jp < 4; jp++) {
                    mma_bf16(accO[jp * 2],     pa_h[c][0], pa_h[c][1], pa_h[c][2], pa_h[c][3],
                             vl[jp][0], vl[jp][1]);
                    mma_bf16(accO[jp * 2 + 1], pa_h[c][0], pa_h[c][1], pa_h[c][2], pa_h[c][3],
                             vl[jp][2], vl[jp][3]);
                }
#pragma unroll
                for (int jp = 0; jp < 4; jp++) {
                    mma_bf16(accO[jp * 2],     pa_h[c][0], pa_h[c][1], pa_h[c][2], pa_h[c][3],
                             vh[jp][0], vh[jp][1]);
                    mma_bf16(accO[jp * 2 + 1], pa_h[c][0], pa_h[c][1], pa_h[c][2], pa_h[c][3],
                             vh[jp][2], vh[jp][3]);
                }
            }
        }
    }

    __syncthreads();       // all PV done

    // ---- cross-warp (wn) reconciliation: stage O, m, l from wn==1
    if (wn == 1) {
#pragma unroll
        for (int j = 0; j < 8; j++) {
            *(float2*)(sSt + (m0 + g) * ST_STR + j * 8 + 2 * tig) =
                make_float2(accO[j][0], accO[j][1]);
            *(float2*)(sSt + (m0 + 8 + g) * ST_STR + j * 8 + 2 * tig) =
                make_float2(accO[j][2], accO[j][3]);
        }
        if (tig == 0) {
            mW[m0 + g] = m0r;      mW[m0 + 8 + g] = m1r;
            lW[m0 + g] = l0r;      lW[m0 + 8 + g] = l1r;
        }
    }
    __syncthreads();
    if (wn == 0) {
        float mo0 = mW[m0 + g],     lo0 = lW[m0 + g];
        float mo1 = mW[m0 + 8 + g], lo1 = lW[m0 + 8 + g];
        float M0 = fmaxf(m0r, mo0), M1 = fmaxf(m1r, mo1);
        float fa0 = __expf(m0r - M0), fb0 = __expf(mo0 - M0);
        float fa1 = __expf(m1r - M1), fb1 = __expf(mo1 - M1);
        float inv0 = 1.0f / (l0r * fa0 + lo0 * fb0);
        float inv1 = 1.0f / (l1r * fa1 + lo1 * fb1);
#pragma unroll
        for (int j = 0; j < 8; j++) {
            float2 o0 = *(const float2*)(sSt + (m0 + g) * ST_STR + j * 8 + 2 * tig);
            float2 o1 = *(const float2*)(sSt + (m0 + 8 + g) * ST_STR + j * 8 + 2 * tig);
            float v0 = (accO[j][0] * fa0 + o0.x * fb0) * inv0;
            float v1 = (accO[j][1] * fa0 + o0.y * fb0) * inv0;
            float v2 = (accO[j][2] * fa1 + o1.x * fb1) * inv1;
            float v3 = (accO[j][3] * fa1 + o1.y * fb1) * inv1;
            int col = hoff + j * 8 + 2 * tig;
            size_t a0 = (rowBase + q0 + m0 + g) * CDIM + col;
            size_t a1 = (rowBase + q0 + m0 + 8 + g) * CDIM + col;
            __nv_bfloat16 hh[2], ll[2];
            split_bf16(v0, hh[0], ll[0]); split_bf16(v1, hh[1], ll[1]);
            *(ushort2*)(g_x2h + a0) = *(ushort2*)hh;
            *(ushort2*)(g_x2l + a0) = *(ushort2*)ll;
            split_bf16(v2, hh[0], ll[0]); split_bf16(v3, hh[1], ll[1]);
            *(ushort2*)(g_x2h + a1) = *(ushort2*)hh;
            *(ushort2*)(g_x2l + a1) = *(ushort2*)ll;
        }
    }
}

// ---------------------------------------------------------------------------
// Launch
// ---------------------------------------------------------------------------
extern "C" void kernel_launch(void* const* d_in, const int* in_sizes, int n_in,
                              void* d_out, int out_size) {
    const float* x         = (const float*)d_in[0];
    const float* w_qkv     = (const float*)d_in[1];
    const float* b_qkv     = (const float*)d_in[2];
    const float* rel_table = (const float*)d_in[3];
    const float* w_proj    = (const float*)d_in[4];
    const float* b_proj    = (const float*)d_in[5];
    float* out = (float*)d_out;

    __nv_bfloat16 *pqh, *pql, *pxh, *pxl, *px2h, *px2l, *pwqh, *pwql, *pwph, *pwpl;
    cudaGetSymbolAddress((void**)&pqh, g_qkvh);
    cudaGetSymbolAddress((void**)&pql, g_qkvl);
    cudaGetSymbolAddress((void**)&pxh, g_xh);
    cudaGetSymbolAddress((void**)&pxl, g_xl);
    cudaGetSymbolAddress((void**)&px2h, g_x2h);
    cudaGetSymbolAddress((void**)&px2l, g_x2l);
    cudaGetSymbolAddress((void**)&pwqh, g_wqkvTh);
    cudaGetSymbolAddress((void**)&pwql, g_wqkvTl);
    cudaGetSymbolAddress((void**)&pwph, g_wprojTh);
    cudaGetSymbolAddress((void**)&pwpl, g_wprojTl);

    cudaFuncSetAttribute(attn_kernel, cudaFuncAttributeMaxDynamicSharedMemorySize,
                         AT_SMEM_BYTES);
    cudaFuncSetAttribute(gemm_bf16x3, cudaFuncAttributeMaxDynamicSharedMemorySize,
                         G_SMEM_BYTES);

    const int N4 = MROWS * CDIM / 4;

    // 0) prepasses
    split_kernel<<<(N4 + 255) / 256, 256>>>(x, pxh, pxl, N4);
    transpose_split_kernel<<<dim3(QKV_COLS / 32, CDIM / 32), dim3(32, 8)>>>(
        w_qkv, pwqh, pwql, CDIM, QKV_COLS);
    transpose_split_kernel<<<dim3(CDIM / 32, CDIM / 32), dim3(32, 8)>>>(
        w_proj, pwph, pwpl, CDIM, CDIM);

    // 1) QKV projection -> hi/lo bf16 output   (launch #4: ncu target)
    gemm_bf16x3<<<dim3(QKV_COLS / 128, MROWS / 128), 256, G_SMEM_BYTES>>>(
        pxh, pxl, pwqh, pwql, b_qkv, nullptr, pqh, pql, QKV_COLS);

    // 2) bias+mask precompute
    biasmask_kernel<<<(HEADS * SEQ * SEQ + 255) / 256, 256>>>(rel_table);

    // 3) attention -> hi/lo split output
    attn_kernel<<<dim3(SEQ / 64, HEADS, BATCH), 256, AT_SMEM_BYTES>>>();

    // 4) output projection -> fp32 out
    gemm_bf16x3<<<dim3(CDIM / 128, MROWS / 128), 256, G_SMEM_BYTES>>>(
        px2h, px2l, pwph, pwpl, b_proj, out, nullptr, nullptr, CDIM);
}

// round 13
// speedup vs baseline: 1.2209x; 1.1176x over previous
#include <cuda_runtime.h>
#include <cuda_bf16.h>
#include <cstdint>

// ---------------------------------------------------------------------------
// Problem dimensions (fixed by the reference)
// ---------------------------------------------------------------------------
#define BATCH     32
#define HEADS     12
#define SEQ       576
#define HD        64
#define CDIM      768
#define MROWS     (BATCH * SEQ)      // 18432
#define QKV_COLS  (3 * CDIM)         // 2304
#define GRID_SZ   24
#define MSIZE     47
#define MASK_D    12
#define SOFT_SCALE 0.125f

// ---------------------------------------------------------------------------
// Scratch (device globals)
// ---------------------------------------------------------------------------
__device__ float g_bm[(size_t)HEADS * SEQ * SEQ];                 // 16 MB
__device__ __nv_bfloat16 g_qkvh[(size_t)MROWS * QKV_COLS];
__device__ __nv_bfloat16 g_qkvl[(size_t)MROWS * QKV_COLS];
__device__ __nv_bfloat16 g_xh[(size_t)MROWS * CDIM];
__device__ __nv_bfloat16 g_xl[(size_t)MROWS * CDIM];
__device__ __nv_bfloat16 g_x2h[(size_t)MROWS * CDIM];
__device__ __nv_bfloat16 g_x2l[(size_t)MROWS * CDIM];
__device__ __nv_bfloat16 g_wqkvTh[(size_t)QKV_COLS * CDIM];
__device__ __nv_bfloat16 g_wqkvTl[(size_t)QKV_COLS * CDIM];
__device__ __nv_bfloat16 g_wprojTh[(size_t)CDIM * CDIM];
__device__ __nv_bfloat16 g_wprojTl[(size_t)CDIM * CDIM];

// ---------------------------------------------------------------------------
// Helpers
// ---------------------------------------------------------------------------
__device__ __forceinline__ void cp_async16(uint32_t smem_dst, const void* gptr) {
    asm volatile("cp.async.cg.shared.global [%0], [%1], 16;"
                 :: "r"(smem_dst), "l"(gptr));
}
__device__ __forceinline__ void cp_commit() { asm volatile("cp.async.commit_group;"); }
__device__ __forceinline__ void cp_wait0()  { asm volatile("cp.async.wait_group 0;"); }
__device__ __forceinline__ void cp_wait1()  { asm volatile("cp.async.wait_group 1;"); }

__device__ __forceinline__ void mma_bf16(
    float* c, uint32_t a0, uint32_t a1, uint32_t a2, uint32_t a3,
    uint32_t b0, uint32_t b1)
{
    asm volatile(
        "mma.sync.aligned.m16n8k16.row.col.f32.bf16.bf16.f32 "
        "{%0,%1,%2,%3}, {%4,%5,%6,%7}, {%8,%9}, {%0,%1,%2,%3};"
        : "+f"(c[0]), "+f"(c[1]), "+f"(c[2]), "+f"(c[3])
        : "r"(a0), "r"(a1), "r"(a2), "r"(a3), "r"(b0), "r"(b1));
}

__device__ __forceinline__ void ldsm_x4(uint32_t& r0, uint32_t& r1,
                                        uint32_t& r2, uint32_t& r3,
                                        uint32_t addr) {
    asm volatile("ldmatrix.sync.aligned.m8n8.x4.shared.b16 {%0,%1,%2,%3}, [%4];"
                 : "=r"(r0), "=r"(r1), "=r"(r2), "=r"(r3) : "r"(addr));
}
__device__ __forceinline__ void ldsm_x4_t(uint32_t& r0, uint32_t& r1,
                                          uint32_t& r2, uint32_t& r3,
                                          uint32_t addr) {
    asm volatile("ldmatrix.sync.aligned.m8n8.x4.trans.shared.b16 {%0,%1,%2,%3}, [%4];"
                 : "=r"(r0), "=r"(r1), "=r"(r2), "=r"(r3) : "r"(addr));
}

__device__ __forceinline__ void split_bf16(float v, __nv_bfloat16& h, __nv_bfloat16& l) {
    h = __float2bfloat16(v);
    l = __float2bfloat16(v - __bfloat162float(h));
}
__device__ __forceinline__ uint32_t pack2(float a, float b) {
    __nv_bfloat162 t = __floats2bfloat162_rn(a, b);
    return *(uint32_t*)&t;
}

// ---------------------------------------------------------------------------
// Prepass kernels
// ---------------------------------------------------------------------------
__global__ void split_kernel(const float* __restrict__ in,
                             __nv_bfloat16* __restrict__ hi,
                             __nv_bfloat16* __restrict__ lo, int n4) {
    int t = blockIdx.x * 256 + threadIdx.x;
    if (t >= n4) return;
    float4 v = *(const float4*)(in + (size_t)t * 4);
    __nv_bfloat16 h[4], l[4];
    split_bf16(v.x, h[0], l[0]);
    split_bf16(v.y, h[1], l[1]);
    split_bf16(v.z, h[2], l[2]);
    split_bf16(v.w, h[3], l[3]);
    *(ushort4*)(hi + (size_t)t * 4) = *(ushort4*)h;
    *(ushort4*)(lo + (size_t)t * 4) = *(ushort4*)l;
}

__global__ void transpose_split_kernel(const float* __restrict__ src,
                                       __nv_bfloat16* __restrict__ dstH,
                                       __nv_bfloat16* __restrict__ dstL,
                                       int R, int C) {
    __shared__ float t[32][33];
    int bx = blockIdx.x * 32, by = blockIdx.y * 32;
#pragma unroll
    for (int i = 0; i < 32; i += 8)
        t[threadIdx.y + i][threadIdx.x] =
            src[(size_t)(by + threadIdx.y + i) * C + bx + threadIdx.x];
    __syncthreads();
#pragma unroll
    for (int i = 0; i < 32; i += 8) {
        float v = t[threadIdx.x][threadIdx.y + i];
        __nv_bfloat16 h, l;
        split_bf16(v, h, l);
        size_t o = (size_t)(bx + threadIdx.y + i) * R + by + threadIdx.x;
        dstH[o] = h;
        dstL[o] = l;
    }
}

__global__ void biasmask_kernel(const float* __restrict__ rel_table) {
    int t = blockIdx.x * 256 + threadIdx.x;
    if (t >= HEADS * SEQ * SEQ) return;
    int h = t / (SEQ * SEQ);
    int r = t - h * (SEQ * SEQ);
    int q = r / SEQ;
    int k = r - q * SEQ;
    int qr = q / GRID_SZ, qc = q - qr * GRID_SZ;
    int kr = k / GRID_SZ, kc = k - kr * GRID_SZ;
    int dr = kr - qr, dc = kc - qc;
    int idx = (dr + GRID_SZ - 1) * MSIZE + (dc + GRID_SZ - 1);
    float v = rel_table[idx * HEADS + h];
    int cheb = max(abs(dr), abs(dc));
    if (cheb > MASK_D) v += -100.0f;
    g_bm[t] = v;
}

// ---------------------------------------------------------------------------
// bf16x3 tensor-core GEMM — 128x128, 256 thr, 2 CTA/SM; MMA-first scheduling
// (next-stage cp.async issue interleaved between the two k16 halves).
// ---------------------------------------------------------------------------
#define KDIM 768
#define GBK  32
#define NST  (KDIM / GBK)
#define TROW 40
#define TILE_BYTES (128 * TROW * 2)
#define STAGE_BYTES (4 * TILE_BYTES)
#define G_SMEM_BYTES (2 * STAGE_BYTES)

__global__ __launch_bounds__(256, 2)
void gemm_bf16x3(const __nv_bfloat16* __restrict__ Ah,
                 const __nv_bfloat16* __restrict__ Al,
                 const __nv_bfloat16* __restrict__ Bh,
                 const __nv_bfloat16* __restrict__ Bl,
                 const float* __restrict__ bias,
                 float* __restrict__ Cf,
                 __nv_bfloat16* __restrict__ Ch,
                 __nv_bfloat16* __restrict__ Cl, int Nt) {
    extern __shared__ __nv_bfloat16 smb[];
    const uint32_t smem0 = (uint32_t)__cvta_generic_to_shared(smb);

    const int tid = threadIdx.x;
    const int wid = tid >> 5;
    const int lane = tid & 31;
    const int g = lane >> 2;
    const int tig = lane & 3;
    const int l8 = lane & 7;
    const int sel = lane >> 3;
    const int wm = wid & 1;
    const int wn = wid >> 1;
    const int tileM = blockIdx.y, tileN = blockIdx.x;

    const __nv_bfloat16* Abh = Ah + (size_t)tileM * 128 * KDIM;
    const __nv_bfloat16* Abl = Al + (size_t)tileM * 128 * KDIM;
    const __nv_bfloat16* Bbh = Bh + (size_t)tileN * 128 * KDIM;
    const __nv_bfloat16* Bbl = Bl + (size_t)tileN * 128 * KDIM;

    const uint32_t aRC = (uint32_t)((wm * 64 + (sel & 1) * 8 + l8) * TROW + (sel >> 1) * 8) * 2;
    const uint32_t bRC = (uint32_t)((wn * 32 + (sel >> 1) * 8 + l8) * TROW + (sel & 1) * 8) * 2;
    const uint32_t aAH = smem0 + 0 * TILE_BYTES + aRC;
    const uint32_t aAL = smem0 + 1 * TILE_BYTES + aRC;
    const uint32_t bAH = smem0 + 2 * TILE_BYTES + bRC;
    const uint32_t bAL = smem0 + 3 * TILE_BYTES + bRC;

    float acc[4][4][4];
#pragma unroll
    for (int i = 0; i < 4; i++)
#pragma unroll
        for (int j = 0; j < 4; j++)
#pragma unroll
            for (int r = 0; r < 4; r++) acc[i][j][r] = 0.0f;

    auto issue = [&](int s, int buf) {
        const int k0 = s * GBK;
        const uint32_t base = smem0 + buf * STAGE_BYTES;
#pragma unroll
        for (int rep = 0; rep < 2; rep++) {
            int c = tid + rep * 256;
            int row = c >> 2, ch = c & 3;
            uint32_t soff = (uint32_t)(row * TROW + ch * 8) * 2;
            size_t goff = (size_t)row * KDIM + k0 + ch * 8;
            cp_async16(base + 0 * TILE_BYTES + soff, Abh + goff);
            cp_async16(base + 1 * TILE_BYTES + soff, Abl + goff);
            cp_async16(base + 2 * TILE_BYTES + soff, Bbh + goff);
            cp_async16(base + 3 * TILE_BYTES + soff, Bbl + goff);
        }
        cp_commit();
    };

    issue(0, 0);

    int buf = 0;
    for (int s = 0; s < NST; s++) {
        cp_wait0();
        __syncthreads();    // stage data visible; prior-stage compute complete

        const uint32_t bo = (uint32_t)buf * STAGE_BYTES;
#pragma unroll
        for (int k16 = 0; k16 < 2; k16++) {
            const uint32_t kk2 = (uint32_t)(k16 * 16) * 2;
            uint32_t bh[4][2], bl[4][2];
#pragma unroll
            for (int jp = 0; jp < 2; jp++) {
                const uint32_t jo = (uint32_t)(jp * 16 * TROW) * 2 + kk2;
                uint32_t t0, t1, t2, t3;
                ldsm_x4(t0, t1, t2, t3, bAH + jo + bo);
                bh[2 * jp][0] = t0; bh[2 * jp][1] = t1;
                bh[2 * jp + 1][0] = t2; bh[2 * jp + 1][1] = t3;
                ldsm_x4(t0, t1, t2, t3, bAL + jo + bo);
                bl[2 * jp][0] = t0; bl[2 * jp][1] = t1;
                bl[2 * jp + 1][0] = t2; bl[2 * jp + 1][1] = t3;
            }
#pragma unroll
            for (int ip = 0; ip < 2; ip++) {
                uint32_t ah[2][4], al[2][4];
#pragma unroll
                for (int ii = 0; ii < 2; ii++) {
                    const uint32_t io = (uint32_t)((2 * ip + ii) * 16 * TROW) * 2 + kk2;
                    ldsm_x4(ah[ii][0], ah[ii][1], ah[ii][2], ah[ii][3], aAH + io + bo);
                    ldsm_x4(al[ii][0], al[ii][1], al[ii][2], al[ii][3], aAL + io + bo);
                }
#pragma unroll
                for (int ii = 0; ii < 2; ii++)
#pragma unroll
                    for (int j = 0; j < 4; j++)
                        mma_bf16(acc[2 * ip + ii][j],
                                 al[ii][0], al[ii][1], al[ii][2], al[ii][3],
                                 bh[j][0], bh[j][1]);
#pragma unroll
                for (int ii = 0; ii < 2; ii++)
#pragma unroll
                    for (int j = 0; j < 4; j++)
                        mma_bf16(acc[2 * ip + ii][j],
                                 ah[ii][0], ah[ii][1], ah[ii][2], ah[ii][3],
                                 bl[j][0], bl[j][1]);
#pragma unroll
                for (int ii = 0; ii < 2; ii++)
#pragma unroll
                    for (int j = 0; j < 4; j++)
                        mma_bf16(acc[2 * ip + ii][j],
                                 ah[ii][0], ah[ii][1], ah[ii][2], ah[ii][3],
                                 bh[j][0], bh[j][1]);
            }
            // interleave next-stage loads between the two k16 halves:
            // MMAs for k16=0 start immediately after the barrier.
            if (k16 == 0 && s + 1 < NST) issue(s + 1, buf ^ 1);
        }
        buf ^= 1;
    }

#pragma unroll
    for (int i = 0; i < 4; i++) {
        const int row = tileM * 128 + wm * 64 + i * 16 + g;
#pragma unroll
        for (int j = 0; j < 4; j++) {
            const int col = tileN * 128 + wn * 32 + j * 8 + 2 * tig;
            const float b0 = bias[col], b1 = bias[col + 1];
            float v0 = acc[i][j][0] + b0, v1 = acc[i][j][1] + b1;
            float v2 = acc[i][j][2] + b0, v3 = acc[i][j][3] + b1;
            if (Cf) {
                *(float2*)(Cf + (size_t)row * Nt + col) = make_float2(v0, v1);
                *(float2*)(Cf + (size_t)(row + 8) * Nt + col) = make_float2(v2, v3);
            } else {
                __nv_bfloat16 h[2], l[2];
                split_bf16(v0, h[0], l[0]); split_bf16(v1, h[1], l[1]);
                *(ushort2*)(Ch + (size_t)row * Nt + col) = *(ushort2*)h;
                *(ushort2*)(Cl + (size_t)row * Nt + col) = *(ushort2*)l;
                split_bf16(v2, h[0], l[0]); split_bf16(v3, h[1], l[1]);
                *(ushort2*)(Ch + (size_t)(row + 8) * Nt + col) = *(ushort2*)h;
                *(ushort2*)(Cl + (size_t)(row + 8) * Nt + col) = *(ushort2*)l;
            }
        }
    }
}

// ---------------------------------------------------------------------------
// Flash attention, bf16x3; per-warp split-KV softmax; double-buffered K
// -> 2 barriers per k-tile.
// ---------------------------------------------------------------------------
#define QK_STR 72
#define NKT    (SEQ / 64)
#define TILE_E (64 * QK_STR)          // bf16 elems per tile

#define OFF_QH  0
#define OFF_QL  (1 * TILE_E)
#define OFF_KH0 (2 * TILE_E)
#define OFF_KL0 (3 * TILE_E)
#define OFF_KH1 (4 * TILE_E)
#define OFF_KL1 (5 * TILE_E)
#define OFF_VH  (6 * TILE_E)
#define OFF_VL  (7 * TILE_E)
#define KBUF_B  (2 * TILE_E * 2)      // bytes between K buffers
#define OFF_F32 (8 * TILE_E)
#define ST_STR  66
#define ST_F    0
#define MW_F    (ST_F + 64 * ST_STR)
#define LW_F    (MW_F + 64)
#define AT_SMEM_BYTES (OFF_F32 * 2 + (LW_F + 64) * 4)

__global__ __launch_bounds__(256, 2) void attn_kernel() {
    extern __shared__ __nv_bfloat16 smraw[];
    float* fb  = (float*)(smraw + OFF_F32);
    float* sSt = fb + ST_F;
    float* mW  = fb + MW_F;
    float* lW  = fb + LW_F;

    const uint32_t smemU = (uint32_t)__cvta_generic_to_shared(smraw);

    const int tid = threadIdx.x;
    const int wid = tid >> 5;
    const int lane = tid & 31;
    const int g = lane >> 2;
    const int tig = lane & 3;
    const int l8 = lane & 7;
    const int sel = lane >> 3;
    const int wm = wid & 3;
    const int wn = wid >> 2;
    const int m0 = wm * 16;
    const int n0 = wn * 32;

    const int qt = blockIdx.x, h = blockIdx.y, b = blockIdx.z;
    const int q0 = qt * 64;
    const int hoff = h * HD;
    const size_t rowBase = (size_t)b * SEQ;

    const int qlo = q0 / GRID_SZ, qhi = (q0 + 63) / GRID_SZ;
    int ktlo = 0, kthi = NKT - 1;
    while (ktlo < NKT && (64 * ktlo + 63) / GRID_SZ < qlo - MASK_D) ktlo++;
    while (kthi >= 0 && (64 * kthi) / GRID_SZ > qhi + MASK_D) kthi--;

    const uint32_t qRC = (uint32_t)((m0 + (sel & 1) * 8 + l8) * QK_STR + (sel >> 1) * 8) * 2;
    const uint32_t kRC = (uint32_t)((n0 + (sel >> 1) * 8 + l8) * QK_STR + (sel & 1) * 8) * 2;
    const uint32_t qAH = smemU + OFF_QH * 2 + qRC;
    const uint32_t qAL = smemU + OFF_QL * 2 + qRC;
    const uint32_t kAH0 = smemU + OFF_KH0 * 2 + kRC;
    const uint32_t kAL0 = smemU + OFF_KL0 * 2 + kRC;

    // ---- prologue: Q (hi/lo) and K(ktlo) -> K buffer 0
    {
#pragma unroll
        for (int rep = 0; rep < 2; rep++) {
            int c = tid + rep * 256;
            int row = c >> 3, ch = c & 7;
            uint32_t soff = (uint32_t)(row * QK_STR + ch * 8) * 2;
            size_t gq = (rowBase + q0 + row) * QKV_COLS + hoff + ch * 8;
            size_t gk = (rowBase + ktlo * 64 + row) * QKV_COLS + CDIM + hoff + ch * 8;
            cp_async16(smemU + OFF_QH * 2 + soff, g_qkvh + gq);
            cp_async16(smemU + OFF_QL * 2 + soff, g_qkvl + gq);
            cp_async16(smemU + OFF_KH0 * 2 + soff, g_qkvh + gk);
            cp_async16(smemU + OFF_KL0 * 2 + soff, g_qkvl + gk);
        }
        cp_commit();
    }

    float m0r = -1e30f, m1r = -1e30f;
    float l0r = 0.0f,   l1r = 0.0f;

    float accO[8][4];
#pragma unroll
    for (int j = 0; j < 8; j++)
#pragma unroll
        for (int r = 0; r < 4; r++) accO[j][r] = 0.0f;

    for (int kt = ktlo; kt <= kthi; kt++) {
        const int k0 = kt * 64;
        const int kb = (kt - ktlo) & 1;
        const uint32_t kboff = (uint32_t)kb * KBUF_B;
        cp_wait0();
        __syncthreads();   // [barrier 1] K(kt) visible; all warps past prev PV / prev S

        float2 bm0[4], bm1[4];
        {
            const float* bmA = g_bm + ((size_t)h * SEQ + (q0 + m0 + g)) * SEQ + k0 + n0 + 2 * tig;
            const float* bmB = bmA + 8 * SEQ;
#pragma unroll
            for (int j = 0; j < 4; j++) {
                bm0[j] = *(const float2*)(bmA + j * 8);
                bm1[j] = *(const float2*)(bmB + j * 8);
            }
        }

        // ---- S = Q @ K^T (bf16x3, pass-separated), K from buffer kb
        float sacc[4][4];
#pragma unroll
        for (int j = 0; j < 4; j++)
#pragma unroll
            for (int r = 0; r < 4; r++) sacc[j][r] = 0.0f;

#pragma unroll
        for (int kk4 = 0; kk4 < 4; kk4++) {
            const uint32_t kk2 = (uint32_t)(kk4 * 16) * 2;
            uint32_t qh0, qh1, qh2, qh3, ql0, ql1, ql2, ql3;
            ldsm_x4(qh0, qh1, qh2, qh3, qAH + kk2);
            ldsm_x4(ql0, ql1, ql2, ql3, qAL + kk2);
            uint32_t kh[4][2], kl[4][2];
#pragma unroll
            for (int jp = 0; jp < 2; jp++) {
                const uint32_t jo = (uint32_t)(jp * 16 * QK_STR) * 2 + kk2;
                uint32_t t0, t1, t2, t3;
                ldsm_x4(t0, t1, t2, t3, kAH0 + kboff + jo);
                kh[2 * jp][0] = t0; kh[2 * jp][1] = t1;
                kh[2 * jp + 1][0] = t2; kh[2 * jp + 1][1] = t3;
                ldsm_x4(t0, t1, t2, t3, kAL0 + kboff + jo);
                kl[2 * jp][0] = t0; kl[2 * jp][1] = t1;
                kl[2 * jp + 1][0] = t2; kl[2 * jp + 1][1] = t3;
            }
#pragma unroll
            for (int j = 0; j < 4; j++)
                mma_bf16(sacc[j], ql0, ql1, ql2, ql3, kh[j][0], kh[j][1]);
#pragma unroll
            for (int j = 0; j < 4; j++)
                mma_bf16(sacc[j], qh0, qh1, qh2, qh3, kl[j][0], kl[j][1]);
#pragma unroll
            for (int j = 0; j < 4; j++)
                mma_bf16(sacc[j], qh0, qh1, qh2, qh3, kh[j][0], kh[j][1]);
        }

        // ---- prefetch V(kt) and K(kt+1)->other K buffer (no barrier needed:
        //      V readers and K[other] readers all finished before barrier 1)
        {
#pragma unroll
            for (int rep = 0; rep < 2; rep++) {
                int c = tid + rep * 256;
                int row = c >> 3, ch = c & 7;
                uint32_t soff = (uint32_t)(row * QK_STR + ch * 8) * 2;
                size_t gv = (rowBase + k0 + row) * QKV_COLS + 2 * CDIM + hoff + ch * 8;
                cp_async16(smemU + OFF_VH * 2 + soff, g_qkvh + gv);
                cp_async16(smemU + OFF_VL * 2 + soff, g_qkvl + gv);
            }
            cp_commit();
            if (kt < kthi) {
                const uint32_t kno = (uint32_t)(kb ^ 1) * KBUF_B;
#pragma unroll
                for (int rep = 0; rep < 2; rep++) {
                    int c = tid + rep * 256;
                    int row = c >> 3, ch = c & 7;
                    uint32_t soff = (uint32_t)(row * QK_STR + ch * 8) * 2;
                    size_t gk = (rowBase + k0 + 64 + row) * QKV_COLS + CDIM + hoff + ch * 8;
                    cp_async16(smemU + OFF_KH0 * 2 + kno + soff, g_qkvh + gk);
                    cp_async16(smemU + OFF_KL0 * 2 + kno + soff, g_qkvl + gk);
                }
            }
            cp_commit();
        }

        // ---- per-warp online softmax (registers + shfl only)
        float pm0 = -1e30f, pm1 = -1e30f;
#pragma unroll
        for (int j = 0; j < 4; j++) {
            sacc[j][0] = fmaf(sacc[j][0], SOFT_SCALE, bm0[j].x);
            sacc[j][1] = fmaf(sacc[j][1], SOFT_SCALE, bm0[j].y);
            sacc[j][2] = fmaf(sacc[j][2], SOFT_SCALE, bm1[j].x);
            sacc[j][3] = fmaf(sacc[j][3], SOFT_SCALE, bm1[j].y);
            pm0 = fmaxf(pm0, fmaxf(sacc[j][0], sacc[j][1]));
            pm1 = fmaxf(pm1, fmaxf(sacc[j][2], sacc[j][3]));
        }
        pm0 = fmaxf(pm0, __shfl_xor_sync(0xffffffffu, pm0, 1));
        pm0 = fmaxf(pm0, __shfl_xor_sync(0xffffffffu, pm0, 2));
        pm1 = fmaxf(pm1, __shfl_xor_sync(0xffffffffu, pm1, 1));
        pm1 = fmaxf(pm1, __shfl_xor_sync(0xffffffffu, pm1, 2));

        float mn0 = fmaxf(m0r, pm0), mn1 = fmaxf(m1r, pm1);
        float sc0 = __expf(m0r - mn0), sc1 = __expf(m1r - mn1);
        m0r = mn0; m1r = mn1;

        uint32_t pa_h[2][4], pa_l[2][4];
        float ps0 = 0.0f, ps1 = 0.0f;
#pragma unroll
        for (int j = 0; j < 4; j++) {
            float e0 = __expf(sacc[j][0] - mn0);
            float e1 = __expf(sacc[j][1] - mn0);
            float e2 = __expf(sacc[j][2] - mn1);
            float e3 = __expf(sacc[j][3] - mn1);
            ps0 += e0 + e1;
            ps1 += e2 + e3;
            float h0 = __bfloat162float(__float2bfloat16(e0));
            float h1 = __bfloat162float(__float2bfloat16(e1));
            float h2 = __bfloat162float(__float2bfloat16(e2));
            float h3 = __bfloat162float(__float2bfloat16(e3));
            const int c = j >> 1;
            const int hi2 = (j & 1) * 2;
            pa_h[c][hi2]     = pack2(h0, h1);
            pa_h[c][hi2 + 1] = pack2(h2, h3);
            pa_l[c][hi2]     = pack2(e0 - h0, e1 - h1);
            pa_l[c][hi2 + 1] = pack2(e2 - h2, e3 - h3);
        }
        ps0 += __shfl_xor_sync(0xffffffffu, ps0, 1);
        ps0 += __shfl_xor_sync(0xffffffffu, ps0, 2);
        ps1 += __shfl_xor_sync(0xffffffffu, ps1, 1);
        ps1 += __shfl_xor_sync(0xffffffffu, ps1, 2);
        l0r = l0r * sc0 + ps0;
        l1r = l1r * sc1 + ps1;

#pragma unroll
        for (int j = 0; j < 8; j++) {
            accO[j][0] *= sc0; accO[j][1] *= sc0;
            accO[j][2] *= sc1; accO[j][3] *= sc1;
        }

        cp_wait1();
        __syncthreads();                       // [barrier 2] V(kt) visible

        // ---- O += P @ V (V frags hoisted, 3 passes)
        {
            const int quad = lane >> 3, lrow = lane & 7;
            const int ksub = (quad & 1) * 8;
            const int csel = (quad >> 1) * 8;
#pragma unroll
            for (int c = 0; c < 2; c++) {
                const int krow = n0 + c * 16 + ksub + lrow;
                uint32_t vh[4][4], vl[4][4];
#pragma unroll
                for (int jp = 0; jp < 4; jp++) {
                    uint32_t vrow = (uint32_t)(krow * QK_STR + jp * 16 + csel) * 2;
                    ldsm_x4_t(vh[jp][0], vh[jp][1], vh[jp][2], vh[jp][3],
                              smemU + OFF_VH * 2 + vrow);
                    ldsm_x4_t(vl[jp][0], vl[jp][1], vl[jp][2], vl[jp][3],
                              smemU + OFF_VL * 2 + vrow);
                }
#pragma unroll
                for (int jp = 0; jp < 4; jp++) {
                    mma_bf16(accO[jp * 2],     pa_l[c][0], pa_l[c][1], pa_l[c][2], pa_l[c][3],
                             vh[jp][0], vh[jp][1]);
                    mma_bf16(accO[jp * 2 + 1], pa_l[c][0], pa_l[c][1], pa_l[c][2], pa_l[c][3],
                             vh[jp][2], vh[jp][3]);
                }
#pragma unroll
                for (int jp = 0; jp < 4; jp++) {
                    mma_bf16(accO[jp * 2],     pa_h[c][0], pa_h[c][1], pa_h[c][2], pa_h[c][3],
                             vl[jp][0], vl[jp][1]);
                    mma_bf16(accO[jp * 2 + 1], pa_h[c][0], pa_h[c][1], pa_h[c][2], pa_h[c][3],
                             vl[jp][2], vl[jp][3]);
                }
#pragma unroll
                for (int jp = 0; jp < 4; jp++) {
                    mma_bf16(accO[jp * 2],     pa_h[c][0], pa_h[c][1], pa_h[c][2], pa_h[c][3],
                             vh[jp][0], vh[jp][1]);
                    mma_bf16(accO[jp * 2 + 1], pa_h[c][0], pa_h[c][1], pa_h[c][2], pa_h[c][3],
                             vh[jp][2], vh[jp][3]);
                }
            }
        }
    }

    __syncthreads();       // all PV done

    // ---- cross-warp (wn) reconciliation
    if (wn == 1) {
#pragma unroll
        for (int j = 0; j < 8; j++) {
            *(float2*)(sSt + (m0 + g) * ST_STR + j * 8 + 2 * tig) =
                make_float2(accO[j][0], accO[j][1]);
            *(float2*)(sSt + (m0 + 8 + g) * ST_STR + j * 8 + 2 * tig) =
                make_float2(accO[j][2], accO[j][3]);
        }
        if (tig == 0) {
            mW[m0 + g] = m0r;      mW[m0 + 8 + g] = m1r;
            lW[m0 + g] = l0r;      lW[m0 + 8 + g] = l1r;
        }
    }
    __syncthreads();
    if (wn == 0) {
        float mo0 = mW[m0 + g],     lo0 = lW[m0 + g];
        float mo1 = mW[m0 + 8 + g], lo1 = lW[m0 + 8 + g];
        float M0 = fmaxf(m0r, mo0), M1 = fmaxf(m1r, mo1);
        float fa0 = __expf(m0r - M0), fb0 = __expf(mo0 - M0);
        float fa1 = __expf(m1r - M1), fb1 = __expf(mo1 - M1);
        float inv0 = 1.0f / (l0r * fa0 + lo0 * fb0);
        float inv1 = 1.0f / (l1r * fa1 + lo1 * fb1);
#pragma unroll
        for (int j = 0; j < 8; j++) {
            float2 o0 = *(const float2*)(sSt + (m0 + g) * ST_STR + j * 8 + 2 * tig);
            float2 o1 = *(const float2*)(sSt + (m0 + 8 + g) * ST_STR + j * 8 + 2 * tig);
            float v0 = (accO[j][0] * fa0 + o0.x * fb0) * inv0;
            float v1 = (accO[j][1] * fa0 + o0.y * fb0) * inv0;
            float v2 = (accO[j][2] * fa1 + o1.x * fb1) * inv1;
            float v3 = (accO[j][3] * fa1 + o1.y * fb1) * inv1;
            int col = hoff + j * 8 + 2 * tig;
            size_t a0 = (rowBase + q0 + m0 + g) * CDIM + col;
            size_t a1 = (rowBase + q0 + m0 + 8 + g) * CDIM + col;
            __nv_bfloat16 hh[2], ll[2];
            split_bf16(v0, hh[0], ll[0]); split_bf16(v1, hh[1], ll[1]);
            *(ushort2*)(g_x2h + a0) = *(ushort2*)hh;
            *(ushort2*)(g_x2l + a0) = *(ushort2*)ll;
            split_bf16(v2, hh[0], ll[0]); split_bf16(v3, hh[1], ll[1]);
            *(ushort2*)(g_x2h + a1) = *(ushort2*)hh;
            *(ushort2*)(g_x2l + a1) = *(ushort2*)ll;
        }
    }
}

// ---------------------------------------------------------------------------
// Launch
// ---------------------------------------------------------------------------
extern "C" void kernel_launch(void* const* d_in, const int* in_sizes, int n_in,
                              void* d_out, int out_size) {
    const float* x         = (const float*)d_in[0];
    const float* w_qkv     = (const float*)d_in[1];
    const float* b_qkv     = (const float*)d_in[2];
    const float* rel_table = (const float*)d_in[3];
    const float* w_proj    = (const float*)d_in[4];
    const float* b_proj    = (const float*)d_in[5];
    float* out = (float*)d_out;

    __nv_bfloat16 *pqh, *pql, *pxh, *pxl, *px2h, *px2l, *pwqh, *pwql, *pwph, *pwpl;
    cudaGetSymbolAddress((void**)&pqh, g_qkvh);
    cudaGetSymbolAddress((void**)&pql, g_qkvl);
    cudaGetSymbolAddress((void**)&pxh, g_xh);
    cudaGetSymbolAddress((void**)&pxl, g_xl);
    cudaGetSymbolAddress((void**)&px2h, g_x2h);
    cudaGetSymbolAddress((void**)&px2l, g_x2l);
    cudaGetSymbolAddress((void**)&pwqh, g_wqkvTh);
    cudaGetSymbolAddress((void**)&pwql, g_wqkvTl);
    cudaGetSymbolAddress((void**)&pwph, g_wprojTh);
    cudaGetSymbolAddress((void**)&pwpl, g_wprojTl);

    cudaFuncSetAttribute(attn_kernel, cudaFuncAttributeMaxDynamicSharedMemorySize,
                         AT_SMEM_BYTES);
    cudaFuncSetAttribute(gemm_bf16x3, cudaFuncAttributeMaxDynamicSharedMemorySize,
                         G_SMEM_BYTES);

    const int N4 = MROWS * CDIM / 4;

    // 0) prepasses
    split_kernel<<<(N4 + 255) / 256, 256>>>(x, pxh, pxl, N4);
    transpose_split_kernel<<<dim3(QKV_COLS / 32, CDIM / 32), dim3(32, 8)>>>(
        w_qkv, pwqh, pwql, CDIM, QKV_COLS);
    transpose_split_kernel<<<dim3(CDIM / 32, CDIM / 32), dim3(32, 8)>>>(
        w_proj, pwph, pwpl, CDIM, CDIM);

    // 1) QKV projection -> hi/lo bf16 output   (launch #4: ncu target)
    gemm_bf16x3<<<dim3(QKV_COLS / 128, MROWS / 128), 256, G_SMEM_BYTES>>>(
        pxh, pxl, pwqh, pwql, b_qkv, nullptr, pqh, pql, QKV_COLS);

    // 2) bias+mask precompute
    biasmask_kernel<<<(HEADS * SEQ * SEQ + 255) / 256, 256>>>(rel_table);

    // 3) attention -> hi/lo split output
    attn_kernel<<<dim3(SEQ / 64, HEADS, BATCH), 256, AT_SMEM_BYTES>>>();

    // 4) output projection -> fp32 out
    gemm_bf16x3<<<dim3(CDIM / 128, MROWS / 128), 256, G_SMEM_BYTES>>>(
        px2h, px2l, pwph, pwpl, b_proj, out, nullptr, nullptr, CDIM);
}

// round 14
// speedup vs baseline: 1.2334x; 1.0102x over previous
#include <cuda_runtime.h>
#include <cuda_bf16.h>
#include <cstdint>

// ---------------------------------------------------------------------------
// Problem dimensions (fixed by the reference)
// ---------------------------------------------------------------------------
#define BATCH     32
#define HEADS     12
#define SEQ       576
#define HD        64
#define CDIM      768
#define MROWS     (BATCH * SEQ)      // 18432
#define QKV_COLS  (3 * CDIM)         // 2304
#define GRID_SZ   24
#define MSIZE     47
#define MASK_D    12
#define SOFT_SCALE 0.125f

// ---------------------------------------------------------------------------
// Scratch (device globals)
// ---------------------------------------------------------------------------
__device__ __nv_bfloat16 g_bmh[(size_t)HEADS * SEQ * SEQ];        // 8 MB (bf16)
__device__ __nv_bfloat16 g_qkvh[(size_t)MROWS * QKV_COLS];
__device__ __nv_bfloat16 g_qkvl[(size_t)MROWS * QKV_COLS];
__device__ __nv_bfloat16 g_xh[(size_t)MROWS * CDIM];
__device__ __nv_bfloat16 g_xl[(size_t)MROWS * CDIM];
__device__ __nv_bfloat16 g_x2h[(size_t)MROWS * CDIM];
__device__ __nv_bfloat16 g_x2l[(size_t)MROWS * CDIM];
__device__ __nv_bfloat16 g_wqkvTh[(size_t)QKV_COLS * CDIM];
__device__ __nv_bfloat16 g_wqkvTl[(size_t)QKV_COLS * CDIM];
__device__ __nv_bfloat16 g_wprojTh[(size_t)CDIM * CDIM];
__device__ __nv_bfloat16 g_wprojTl[(size_t)CDIM * CDIM];

// ---------------------------------------------------------------------------
// Helpers
// ---------------------------------------------------------------------------
__device__ __forceinline__ void cp_async16(uint32_t smem_dst, const void* gptr) {
    asm volatile("cp.async.cg.shared.global [%0], [%1], 16;"
                 :: "r"(smem_dst), "l"(gptr));
}
__device__ __forceinline__ void cp_commit() { asm volatile("cp.async.commit_group;"); }
__device__ __forceinline__ void cp_wait0()  { asm volatile("cp.async.wait_group 0;"); }
__device__ __forceinline__ void cp_wait1()  { asm volatile("cp.async.wait_group 1;"); }

__device__ __forceinline__ void mma_bf16(
    float* c, uint32_t a0, uint32_t a1, uint32_t a2, uint32_t a3,
    uint32_t b0, uint32_t b1)
{
    asm volatile(
        "mma.sync.aligned.m16n8k16.row.col.f32.bf16.bf16.f32 "
        "{%0,%1,%2,%3}, {%4,%5,%6,%7}, {%8,%9}, {%0,%1,%2,%3};"
        : "+f"(c[0]), "+f"(c[1]), "+f"(c[2]), "+f"(c[3])
        : "r"(a0), "r"(a1), "r"(a2), "r"(a3), "r"(b0), "r"(b1));
}

__device__ __forceinline__ void ldsm_x4(uint32_t& r0, uint32_t& r1,
                                        uint32_t& r2, uint32_t& r3,
                                        uint32_t addr) {
    asm volatile("ldmatrix.sync.aligned.m8n8.x4.shared.b16 {%0,%1,%2,%3}, [%4];"
                 : "=r"(r0), "=r"(r1), "=r"(r2), "=r"(r3) : "r"(addr));
}
__device__ __forceinline__ void ldsm_x4_t(uint32_t& r0, uint32_t& r1,
                                          uint32_t& r2, uint32_t& r3,
                                          uint32_t addr) {
    asm volatile("ldmatrix.sync.aligned.m8n8.x4.trans.shared.b16 {%0,%1,%2,%3}, [%4];"
                 : "=r"(r0), "=r"(r1), "=r"(r2), "=r"(r3) : "r"(addr));
}

__device__ __forceinline__ void split_bf16(float v, __nv_bfloat16& h, __nv_bfloat16& l) {
    h = __float2bfloat16(v);
    l = __float2bfloat16(v - __bfloat162float(h));
}
__device__ __forceinline__ uint32_t pack2(float a, float b) {
    __nv_bfloat162 t = __floats2bfloat162_rn(a, b);
    return *(uint32_t*)&t;
}
__device__ __forceinline__ float2 bf2f(uint32_t u) {
    return __bfloat1622float2(*(__nv_bfloat162*)&u);
}

// ---------------------------------------------------------------------------
// Prepass kernels
// ---------------------------------------------------------------------------
__global__ void split_kernel(const float* __restrict__ in,
                             __nv_bfloat16* __restrict__ hi,
                             __nv_bfloat16* __restrict__ lo, int n4) {
    int t = blockIdx.x * 256 + threadIdx.x;
    if (t >= n4) return;
    float4 v = *(const float4*)(in + (size_t)t * 4);
    __nv_bfloat16 h[4], l[4];
    split_bf16(v.x, h[0], l[0]);
    split_bf16(v.y, h[1], l[1]);
    split_bf16(v.z, h[2], l[2]);
    split_bf16(v.w, h[3], l[3]);
    *(ushort4*)(hi + (size_t)t * 4) = *(ushort4*)h;
    *(ushort4*)(lo + (size_t)t * 4) = *(ushort4*)l;
}

__global__ void transpose_split_kernel(const float* __restrict__ src,
                                       __nv_bfloat16* __restrict__ dstH,
                                       __nv_bfloat16* __restrict__ dstL,
                                       int R, int C) {
    __shared__ float t[32][33];
    int bx = blockIdx.x * 32, by = blockIdx.y * 32;
#pragma unroll
    for (int i = 0; i < 32; i += 8)
        t[threadIdx.y + i][threadIdx.x] =
            src[(size_t)(by + threadIdx.y + i) * C + bx + threadIdx.x];
    __syncthreads();
#pragma unroll
    for (int i = 0; i < 32; i += 8) {
        float v = t[threadIdx.x][threadIdx.y + i];
        __nv_bfloat16 h, l;
        split_bf16(v, h, l);
        size_t o = (size_t)(bx + threadIdx.y + i) * R + by + threadIdx.x;
        dstH[o] = h;
        dstL[o] = l;
    }
}

__global__ void biasmask_kernel(const float* __restrict__ rel_table) {
    int t = blockIdx.x * 256 + threadIdx.x;
    if (t >= HEADS * SEQ * SEQ) return;
    int h = t / (SEQ * SEQ);
    int r = t - h * (SEQ * SEQ);
    int q = r / SEQ;
    int k = r - q * SEQ;
    int qr = q / GRID_SZ, qc = q - qr * GRID_SZ;
    int kr = k / GRID_SZ, kc = k - kr * GRID_SZ;
    int dr = kr - qr, dc = kc - qc;
    int idx = (dr + GRID_SZ - 1) * MSIZE + (dc + GRID_SZ - 1);
    float v = rel_table[idx * HEADS + h];
    int cheb = max(abs(dr), abs(dc));
    if (cheb > MASK_D) v += -100.0f;
    g_bmh[t] = __float2bfloat16(v);
}

// ---------------------------------------------------------------------------
// bf16x3 tensor-core GEMM — R12 config (unchanged; 72% tensor, best known)
// ---------------------------------------------------------------------------
#define KDIM 768
#define GBK  32
#define NST  (KDIM / GBK)
#define TROW 40
#define TILE_BYTES (128 * TROW * 2)
#define STAGE_BYTES (4 * TILE_BYTES)
#define G_SMEM_BYTES (2 * STAGE_BYTES)

__global__ __launch_bounds__(256, 2)
void gemm_bf16x3(const __nv_bfloat16* __restrict__ Ah,
                 const __nv_bfloat16* __restrict__ Al,
                 const __nv_bfloat16* __restrict__ Bh,
                 const __nv_bfloat16* __restrict__ Bl,
                 const float* __restrict__ bias,
                 float* __restrict__ Cf,
                 __nv_bfloat16* __restrict__ Ch,
                 __nv_bfloat16* __restrict__ Cl, int Nt) {
    extern __shared__ __nv_bfloat16 smb[];
    const uint32_t smem0 = (uint32_t)__cvta_generic_to_shared(smb);

    const int tid = threadIdx.x;
    const int wid = tid >> 5;
    const int lane = tid & 31;
    const int g = lane >> 2;
    const int tig = lane & 3;
    const int l8 = lane & 7;
    const int sel = lane >> 3;
    const int wm = wid & 1;
    const int wn = wid >> 1;
    const int tileM = blockIdx.y, tileN = blockIdx.x;

    const __nv_bfloat16* Abh = Ah + (size_t)tileM * 128 * KDIM;
    const __nv_bfloat16* Abl = Al + (size_t)tileM * 128 * KDIM;
    const __nv_bfloat16* Bbh = Bh + (size_t)tileN * 128 * KDIM;
    const __nv_bfloat16* Bbl = Bl + (size_t)tileN * 128 * KDIM;

    const uint32_t aRC = (uint32_t)((wm * 64 + (sel & 1) * 8 + l8) * TROW + (sel >> 1) * 8) * 2;
    const uint32_t bRC = (uint32_t)((wn * 32 + (sel >> 1) * 8 + l8) * TROW + (sel & 1) * 8) * 2;
    const uint32_t aAH = smem0 + 0 * TILE_BYTES + aRC;
    const uint32_t aAL = smem0 + 1 * TILE_BYTES + aRC;
    const uint32_t bAH = smem0 + 2 * TILE_BYTES + bRC;
    const uint32_t bAL = smem0 + 3 * TILE_BYTES + bRC;

    float acc[4][4][4];
#pragma unroll
    for (int i = 0; i < 4; i++)
#pragma unroll
        for (int j = 0; j < 4; j++)
#pragma unroll
            for (int r = 0; r < 4; r++) acc[i][j][r] = 0.0f;

    auto issue = [&](int s, int buf) {
        const int k0 = s * GBK;
        const uint32_t base = smem0 + buf * STAGE_BYTES;
#pragma unroll
        for (int rep = 0; rep < 2; rep++) {
            int c = tid + rep * 256;
            int row = c >> 2, ch = c & 3;
            uint32_t soff = (uint32_t)(row * TROW + ch * 8) * 2;
            size_t goff = (size_t)row * KDIM + k0 + ch * 8;
            cp_async16(base + 0 * TILE_BYTES + soff, Abh + goff);
            cp_async16(base + 1 * TILE_BYTES + soff, Abl + goff);
            cp_async16(base + 2 * TILE_BYTES + soff, Bbh + goff);
            cp_async16(base + 3 * TILE_BYTES + soff, Bbl + goff);
        }
        cp_commit();
    };

    issue(0, 0);

    int buf = 0;
    for (int s = 0; s < NST; s++) {
        cp_wait0();
        __syncthreads();

        const uint32_t bo = (uint32_t)buf * STAGE_BYTES;
#pragma unroll
        for (int k16 = 0; k16 < 2; k16++) {
            const uint32_t kk2 = (uint32_t)(k16 * 16) * 2;
            uint32_t bh[4][2], bl[4][2];
#pragma unroll
            for (int jp = 0; jp < 2; jp++) {
                const uint32_t jo = (uint32_t)(jp * 16 * TROW) * 2 + kk2;
                uint32_t t0, t1, t2, t3;
                ldsm_x4(t0, t1, t2, t3, bAH + jo + bo);
                bh[2 * jp][0] = t0; bh[2 * jp][1] = t1;
                bh[2 * jp + 1][0] = t2; bh[2 * jp + 1][1] = t3;
                ldsm_x4(t0, t1, t2, t3, bAL + jo + bo);
                bl[2 * jp][0] = t0; bl[2 * jp][1] = t1;
                bl[2 * jp + 1][0] = t2; bl[2 * jp + 1][1] = t3;
            }
#pragma unroll
            for (int ip = 0; ip < 2; ip++) {
                uint32_t ah[2][4], al[2][4];
#pragma unroll
                for (int ii = 0; ii < 2; ii++) {
                    const uint32_t io = (uint32_t)((2 * ip + ii) * 16 * TROW) * 2 + kk2;
                    ldsm_x4(ah[ii][0], ah[ii][1], ah[ii][2], ah[ii][3], aAH + io + bo);
                    ldsm_x4(al[ii][0], al[ii][1], al[ii][2], al[ii][3], aAL + io + bo);
                }
#pragma unroll
                for (int ii = 0; ii < 2; ii++)
#pragma unroll
                    for (int j = 0; j < 4; j++)
                        mma_bf16(acc[2 * ip + ii][j],
                                 al[ii][0], al[ii][1], al[ii][2], al[ii][3],
                                 bh[j][0], bh[j][1]);
#pragma unroll
                for (int ii = 0; ii < 2; ii++)
#pragma unroll
                    for (int j = 0; j < 4; j++)
                        mma_bf16(acc[2 * ip + ii][j],
                                 ah[ii][0], ah[ii][1], ah[ii][2], ah[ii][3],
                                 bl[j][0], bl[j][1]);
#pragma unroll
                for (int ii = 0; ii < 2; ii++)
#pragma unroll
                    for (int j = 0; j < 4; j++)
                        mma_bf16(acc[2 * ip + ii][j],
                                 ah[ii][0], ah[ii][1], ah[ii][2], ah[ii][3],
                                 bh[j][0], bh[j][1]);
            }
            if (k16 == 0 && s + 1 < NST) issue(s + 1, buf ^ 1);
        }
        buf ^= 1;
    }

#pragma unroll
    for (int i = 0; i < 4; i++) {
        const int row = tileM * 128 + wm * 64 + i * 16 + g;
#pragma unroll
        for (int j = 0; j < 4; j++) {
            const int col = tileN * 128 + wn * 32 + j * 8 + 2 * tig;
            const float b0 = bias[col], b1 = bias[col + 1];
            float v0 = acc[i][j][0] + b0, v1 = acc[i][j][1] + b1;
            float v2 = acc[i][j][2] + b0, v3 = acc[i][j][3] + b1;
            if (Cf) {
                *(float2*)(Cf + (size_t)row * Nt + col) = make_float2(v0, v1);
                *(float2*)(Cf + (size_t)(row + 8) * Nt + col) = make_float2(v2, v3);
            } else {
                __nv_bfloat16 h[2], l[2];
                split_bf16(v0, h[0], l[0]); split_bf16(v1, h[1], l[1]);
                *(ushort2*)(Ch + (size_t)row * Nt + col) = *(ushort2*)h;
                *(ushort2*)(Cl + (size_t)row * Nt + col) = *(ushort2*)l;
                split_bf16(v2, h[0], l[0]); split_bf16(v3, h[1], l[1]);
                *(ushort2*)(Ch + (size_t)(row + 8) * Nt + col) = *(ushort2*)h;
                *(ushort2*)(Cl + (size_t)(row + 8) * Nt + col) = *(ushort2*)l;
            }
        }
    }
}

// ---------------------------------------------------------------------------
// Flash attention: 128-q-row tiles, 8 warps x 16 rows x full 64 keys.
// Per-warp online softmax (registers+shfl), double-buffered K, bf16 bias.
// No cross-warp reconciliation. Last block (qt==4) has 64 rows; warps 4-7
// mirror warps 0-3 with stores predicated off.
// ---------------------------------------------------------------------------
#define QK_STR 72
#define T64    (64 * QK_STR)           // 4608 bf16 elems

#define OFF_QH  0
#define OFF_QL  (128 * QK_STR)         // 9216
#define OFF_KH0 (2 * 128 * QK_STR)     // 18432
#define OFF_KL0 (OFF_KH0 + T64)
#define OFF_VH  (OFF_KH0 + 4 * T64)    // 36864
#define OFF_VL  (OFF_VH + T64)
#define KBUF_B  (2 * T64 * 2)          // 18432 bytes between K buffers
#define AT_SMEM_BYTES ((OFF_VL + T64) * 2)   // 92160

__global__ __launch_bounds__(256, 2) void attn_kernel() {
    extern __shared__ __nv_bfloat16 smraw[];
    const uint32_t smemU = (uint32_t)__cvta_generic_to_shared(smraw);

    const int tid = threadIdx.x;
    const int wid = tid >> 5;
    const int lane = tid & 31;
    const int g = lane >> 2;
    const int tig = lane & 3;
    const int l8 = lane & 7;
    const int sel = lane >> 3;

    const int qt = blockIdx.x, h = blockIdx.y, b = blockIdx.z;
    const bool full = (qt < 4);
    const int q0 = qt * 128;
    const int qrows = full ? 128 : 64;
    const int m0 = (full ? wid : (wid & 3)) * 16;
    const int hoff = h * HD;
    const size_t rowBase = (size_t)b * SEQ;

    const int qlo = q0 / GRID_SZ, qhi = (q0 + qrows - 1) / GRID_SZ;
    int ktlo = 0, kthi = (SEQ / 64) - 1;
    while (ktlo < SEQ / 64 && (64 * ktlo + 63) / GRID_SZ < qlo - MASK_D) ktlo++;
    while (kthi >= 0 && (64 * kthi) / GRID_SZ > qhi + MASK_D) kthi--;

    const uint32_t qRC = (uint32_t)((m0 + (sel & 1) * 8 + l8) * QK_STR + (sel >> 1) * 8) * 2;
    const uint32_t kRC = (uint32_t)(((sel >> 1) * 8 + l8) * QK_STR + (sel & 1) * 8) * 2;
    const uint32_t qAH = smemU + OFF_QH * 2 + qRC;
    const uint32_t qAL = smemU + OFF_QL * 2 + qRC;
    const uint32_t kAH0 = smemU + OFF_KH0 * 2 + kRC;
    const uint32_t kAL0 = smemU + OFF_KL0 * 2 + kRC;

    // ---- prologue: Q (hi/lo, up to 128 rows) and K(ktlo) -> buffer 0
    {
#pragma unroll
        for (int rep = 0; rep < 4; rep++) {
            int c = tid + rep * 256;
            int row = c >> 3, ch = c & 7;
            if (row < qrows) {
                uint32_t soff = (uint32_t)(row * QK_STR + ch * 8) * 2;
                size_t gq = (rowBase + q0 + row) * QKV_COLS + hoff + ch * 8;
                cp_async16(smemU + OFF_QH * 2 + soff, g_qkvh + gq);
                cp_async16(smemU + OFF_QL * 2 + soff, g_qkvl + gq);
            }
        }
#pragma unroll
        for (int rep = 0; rep < 2; rep++) {
            int c = tid + rep * 256;
            int row = c >> 3, ch = c & 7;
            uint32_t soff = (uint32_t)(row * QK_STR + ch * 8) * 2;
            size_t gk = (rowBase + ktlo * 64 + row) * QKV_COLS + CDIM + hoff + ch * 8;
            cp_async16(smemU + OFF_KH0 * 2 + soff, g_qkvh + gk);
            cp_async16(smemU + OFF_KL0 * 2 + soff, g_qkvl + gk);
        }
        cp_commit();
    }

    float m0r = -1e30f, m1r = -1e30f;
    float l0r = 0.0f,   l1r = 0.0f;

    float accO[8][4];
#pragma unroll
    for (int j = 0; j < 8; j++)
#pragma unroll
        for (int r = 0; r < 4; r++) accO[j][r] = 0.0f;

    for (int kt = ktlo; kt <= kthi; kt++) {
        const int k0 = kt * 64;
        const uint32_t kboff = (uint32_t)((kt - ktlo) & 1) * KBUF_B;
        cp_wait0();
        __syncthreads();   // [barrier 1] K(kt) visible; all warps past prev PV

        // ---- bias/mask tile (bf16 pairs) into registers
        uint32_t bmu0[8], bmu1[8];
        {
            const __nv_bfloat16* bmA =
                g_bmh + ((size_t)h * SEQ + (q0 + m0 + g)) * SEQ + k0 + 2 * tig;
            const __nv_bfloat16* bmB = bmA + 8 * SEQ;
#pragma unroll
            for (int j = 0; j < 8; j++) {
                bmu0[j] = *(const uint32_t*)(bmA + j * 8);
                bmu1[j] = *(const uint32_t*)(bmB + j * 8);
            }
        }

        // ---- S = Q @ K^T over 64 keys (bf16x3, pass-separated per 4-j half)
        float sacc[8][4];
#pragma unroll
        for (int j = 0; j < 8; j++)
#pragma unroll
            for (int r = 0; r < 4; r++) sacc[j][r] = 0.0f;

#pragma unroll
        for (int kk4 = 0; kk4 < 4; kk4++) {
            const uint32_t kk2 = (uint32_t)(kk4 * 16) * 2;
            uint32_t qh0, qh1, qh2, qh3, ql0, ql1, ql2, ql3;
            ldsm_x4(qh0, qh1, qh2, qh3, qAH + kk2);
            ldsm_x4(ql0, ql1, ql2, ql3, qAL + kk2);
#pragma unroll
            for (int nh = 0; nh < 2; nh++) {
                const uint32_t no = (uint32_t)(nh * 32 * QK_STR) * 2;
                uint32_t kh[4][2], kl[4][2];
#pragma unroll
                for (int jp = 0; jp < 2; jp++) {
                    const uint32_t jo = no + (uint32_t)(jp * 16 * QK_STR) * 2 + kk2;
                    uint32_t t0, t1, t2, t3;
                    ldsm_x4(t0, t1, t2, t3, kAH0 + kboff + jo);
                    kh[2 * jp][0] = t0; kh[2 * jp][1] = t1;
                    kh[2 * jp + 1][0] = t2; kh[2 * jp + 1][1] = t3;
                    ldsm_x4(t0, t1, t2, t3, kAL0 + kboff + jo);
                    kl[2 * jp][0] = t0; kl[2 * jp][1] = t1;
                    kl[2 * jp + 1][0] = t2; kl[2 * jp + 1][1] = t3;
                }
                float* sa = &sacc[nh * 4][0];
#pragma unroll
                for (int j = 0; j < 4; j++)
                    mma_bf16(sa + 4 * j, ql0, ql1, ql2, ql3, kh[j][0], kh[j][1]);
#pragma unroll
                for (int j = 0; j < 4; j++)
                    mma_bf16(sa + 4 * j, qh0, qh1, qh2, qh3, kl[j][0], kl[j][1]);
#pragma unroll
                for (int j = 0; j < 4; j++)
                    mma_bf16(sa + 4 * j, qh0, qh1, qh2, qh3, kh[j][0], kh[j][1]);
            }
        }

        // ---- prefetch V(kt) and K(kt+1)->other buffer (no barrier needed)
        {
#pragma unroll
            for (int rep = 0; rep < 2; rep++) {
                int c = tid + rep * 256;
                int row = c >> 3, ch = c & 7;
                uint32_t soff = (uint32_t)(row * QK_STR + ch * 8) * 2;
                size_t gv = (rowBase + k0 + row) * QKV_COLS + 2 * CDIM + hoff + ch * 8;
                cp_async16(smemU + OFF_VH * 2 + soff, g_qkvh + gv);
                cp_async16(smemU + OFF_VL * 2 + soff, g_qkvl + gv);
            }
            cp_commit();
            if (kt < kthi) {
                const uint32_t kno = kboff ^ KBUF_B;
#pragma unroll
                for (int rep = 0; rep < 2; rep++) {
                    int c = tid + rep * 256;
                    int row = c >> 3, ch = c & 7;
                    uint32_t soff = (uint32_t)(row * QK_STR + ch * 8) * 2;
                    size_t gk = (rowBase + k0 + 64 + row) * QKV_COLS + CDIM + hoff + ch * 8;
                    cp_async16(smemU + OFF_KH0 * 2 + kno + soff, g_qkvh + gk);
                    cp_async16(smemU + OFF_KL0 * 2 + kno + soff, g_qkvl + gk);
                }
            }
            cp_commit();
        }

        // ---- per-warp online softmax over 64 keys
        float pm0 = -1e30f, pm1 = -1e30f;
#pragma unroll
        for (int j = 0; j < 8; j++) {
            float2 ba = bf2f(bmu0[j]);
            float2 bb = bf2f(bmu1[j]);
            sacc[j][0] = fmaf(sacc[j][0], SOFT_SCALE, ba.x);
            sacc[j][1] = fmaf(sacc[j][1], SOFT_SCALE, ba.y);
            sacc[j][2] = fmaf(sacc[j][2], SOFT_SCALE, bb.x);
            sacc[j][3] = fmaf(sacc[j][3], SOFT_SCALE, bb.y);
            pm0 = fmaxf(pm0, fmaxf(sacc[j][0], sacc[j][1]));
            pm1 = fmaxf(pm1, fmaxf(sacc[j][2], sacc[j][3]));
        }
        pm0 = fmaxf(pm0, __shfl_xor_sync(0xffffffffu, pm0, 1));
        pm0 = fmaxf(pm0, __shfl_xor_sync(0xffffffffu, pm0, 2));
        pm1 = fmaxf(pm1, __shfl_xor_sync(0xffffffffu, pm1, 1));
        pm1 = fmaxf(pm1, __shfl_xor_sync(0xffffffffu, pm1, 2));

        float mn0 = fmaxf(m0r, pm0), mn1 = fmaxf(m1r, pm1);
        float sc0 = __expf(m0r - mn0), sc1 = __expf(m1r - mn1);
        m0r = mn0; m1r = mn1;

        uint32_t pa_h[4][4], pa_l[4][4];
        float ps0 = 0.0f, ps1 = 0.0f;
#pragma unroll
        for (int j = 0; j < 8; j++) {
            float e0 = __expf(sacc[j][0] - mn0);
            float e1 = __expf(sacc[j][1] - mn0);
            float e2 = __expf(sacc[j][2] - mn1);
            float e3 = __expf(sacc[j][3] - mn1);
            ps0 += e0 + e1;
            ps1 += e2 + e3;
            float h0 = __bfloat162float(__float2bfloat16(e0));
            float h1 = __bfloat162float(__float2bfloat16(e1));
            float h2 = __bfloat162float(__float2bfloat16(e2));
            float h3 = __bfloat162float(__float2bfloat16(e3));
            const int c = j >> 1;
            const int hi2 = (j & 1) * 2;
            pa_h[c][hi2]     = pack2(h0, h1);
            pa_h[c][hi2 + 1] = pack2(h2, h3);
            pa_l[c][hi2]     = pack2(e0 - h0, e1 - h1);
            pa_l[c][hi2 + 1] = pack2(e2 - h2, e3 - h3);
        }
        ps0 += __shfl_xor_sync(0xffffffffu, ps0, 1);
        ps0 += __shfl_xor_sync(0xffffffffu, ps0, 2);
        ps1 += __shfl_xor_sync(0xffffffffu, ps1, 1);
        ps1 += __shfl_xor_sync(0xffffffffu, ps1, 2);
        l0r = l0r * sc0 + ps0;
        l1r = l1r * sc1 + ps1;

#pragma unroll
        for (int j = 0; j < 8; j++) {
            accO[j][0] *= sc0; accO[j][1] *= sc0;
            accO[j][2] *= sc1; accO[j][3] *= sc1;
        }

        cp_wait1();
        __syncthreads();                       // [barrier 2] V(kt) visible

        // ---- O += P @ V over all 64 keys (c = 16-key chunks)
        {
            const int quad = lane >> 3, lrow = lane & 7;
            const int ksub = (quad & 1) * 8;
            const int csel = (quad >> 1) * 8;
#pragma unroll
            for (int c = 0; c < 4; c++) {
                const int krow = c * 16 + ksub + lrow;
#pragma unroll
                for (int jph = 0; jph < 2; jph++) {
                    uint32_t vh[2][4], vl[2][4];
#pragma unroll
                    for (int jj = 0; jj < 2; jj++) {
                        const int jp = jph * 2 + jj;
                        uint32_t vrow = (uint32_t)(krow * QK_STR + jp * 16 + csel) * 2;
                        ldsm_x4_t(vh[jj][0], vh[jj][1], vh[jj][2], vh[jj][3],
                                  smemU + OFF_VH * 2 + vrow);
                        ldsm_x4_t(vl[jj][0], vl[jj][1], vl[jj][2], vl[jj][3],
                                  smemU + OFF_VL * 2 + vrow);
                    }
#pragma unroll
                    for (int jj = 0; jj < 2; jj++) {
                        const int jp = jph * 2 + jj;
                        mma_bf16(accO[jp * 2],     pa_l[c][0], pa_l[c][1], pa_l[c][2], pa_l[c][3],
                                 vh[jj][0], vh[jj][1]);
                        mma_bf16(accO[jp * 2 + 1], pa_l[c][0], pa_l[c][1], pa_l[c][2], pa_l[c][3],
                                 vh[jj][2], vh[jj][3]);
                    }
#pragma unroll
                    for (int jj = 0; jj < 2; jj++) {
                        const int jp = jph * 2 + jj;
                        mma_bf16(accO[jp * 2],     pa_h[c][0], pa_h[c][1], pa_h[c][2], pa_h[c][3],
                                 vl[jj][0], vl[jj][1]);
                        mma_bf16(accO[jp * 2 + 1], pa_h[c][0], pa_h[c][1], pa_h[c][2], pa_h[c][3],
                                 vl[jj][2], vl[jj][3]);
                    }
#pragma unroll
                    for (int jj = 0; jj < 2; jj++) {
                        const int jp = jph * 2 + jj;
                        mma_bf16(accO[jp * 2],     pa_h[c][0], pa_h[c][1], pa_h[c][2], pa_h[c][3],
                                 vh[jj][0], vh[jj][1]);
                        mma_bf16(accO[jp * 2 + 1], pa_h[c][0], pa_h[c][1], pa_h[c][2], pa_h[c][3],
                                 vh[jj][2], vh[jj][3]);
                    }
                }
            }
        }
    }

    // ---- normalize + hi/lo split store (no reconciliation)
    if (full || wid < 4) {
        float inv0 = 1.0f / l0r;
        float inv1 = 1.0f / l1r;
#pragma unroll
        for (int j = 0; j < 8; j++) {
            float v0 = accO[j][0] * inv0;
            float v1 = accO[j][1] * inv0;
            float v2 = accO[j][2] * inv1;
            float v3 = accO[j][3] * inv1;
            int col = hoff + j * 8 + 2 * tig;
            size_t a0 = (rowBase + q0 + m0 + g) * CDIM + col;
            size_t a1 = (rowBase + q0 + m0 + 8 + g) * CDIM + col;
            __nv_bfloat16 hh[2], ll[2];
            split_bf16(v0, hh[0], ll[0]); split_bf16(v1, hh[1], ll[1]);
            *(ushort2*)(g_x2h + a0) = *(ushort2*)hh;
            *(ushort2*)(g_x2l + a0) = *(ushort2*)ll;
            split_bf16(v2, hh[0], ll[0]); split_bf16(v3, hh[1], ll[1]);
            *(ushort2*)(g_x2h + a1) = *(ushort2*)hh;
            *(ushort2*)(g_x2l + a1) = *(ushort2*)ll;
        }
    }
}

// ---------------------------------------------------------------------------
// Launch
// ---------------------------------------------------------------------------
extern "C" void kernel_launch(void* const* d_in, const int* in_sizes, int n_in,
                              void* d_out, int out_size) {
    const float* x         = (const float*)d_in[0];
    const float* w_qkv     = (const float*)d_in[1];
    const float* b_qkv     = (const float*)d_in[2];
    const float* rel_table = (const float*)d_in[3];
    const float* w_proj    = (const float*)d_in[4];
    const float* b_proj    = (const float*)d_in[5];
    float* out = (float*)d_out;

    __nv_bfloat16 *pqh, *pql, *pxh, *pxl, *px2h, *px2l, *pwqh, *pwql, *pwph, *pwpl;
    cudaGetSymbolAddress((void**)&pqh, g_qkvh);
    cudaGetSymbolAddress((void**)&pql, g_qkvl);
    cudaGetSymbolAddress((void**)&pxh, g_xh);
    cudaGetSymbolAddress((void**)&pxl, g_xl);
    cudaGetSymbolAddress((void**)&px2h, g_x2h);
    cudaGetSymbolAddress((void**)&px2l, g_x2l);
    cudaGetSymbolAddress((void**)&pwqh, g_wqkvTh);
    cudaGetSymbolAddress((void**)&pwql, g_wqkvTl);
    cudaGetSymbolAddress((void**)&pwph, g_wprojTh);
    cudaGetSymbolAddress((void**)&pwpl, g_wprojTl);

    cudaFuncSetAttribute(attn_kernel, cudaFuncAttributeMaxDynamicSharedMemorySize,
                         AT_SMEM_BYTES);
    cudaFuncSetAttribute(gemm_bf16x3, cudaFuncAttributeMaxDynamicSharedMemorySize,
                         G_SMEM_BYTES);

    const int N4 = MROWS * CDIM / 4;

    // 0) prepasses
    split_kernel<<<(N4 + 255) / 256, 256>>>(x, pxh, pxl, N4);
    transpose_split_kernel<<<dim3(QKV_COLS / 32, CDIM / 32), dim3(32, 8)>>>(
        w_qkv, pwqh, pwql, CDIM, QKV_COLS);
    transpose_split_kernel<<<dim3(CDIM / 32, CDIM / 32), dim3(32, 8)>>>(
        w_proj, pwph, pwpl, CDIM, CDIM);

    // 1) QKV projection -> hi/lo bf16 output   (launch #4: ncu target)
    gemm_bf16x3<<<dim3(QKV_COLS / 128, MROWS / 128), 256, G_SMEM_BYTES>>>(
        pxh, pxl, pwqh, pwql, b_qkv, nullptr, pqh, pql, QKV_COLS);

    // 2) bias+mask precompute (bf16)
    biasmask_kernel<<<(HEADS * SEQ * SEQ + 255) / 256, 256>>>(rel_table);

    // 3) attention -> hi/lo split output  (5 q-tiles: 4x128 + 1x64 rows)
    attn_kernel<<<dim3(5, HEADS, BATCH), 256, AT_SMEM_BYTES>>>();

    // 4) output projection -> fp32 out
    gemm_bf16x3<<<dim3(CDIM / 128, MROWS / 128), 256, G_SMEM_BYTES>>>(
        px2h, px2l, pwph, pwpl, b_proj, out, nullptr, nullptr, CDIM);
}